// round 1
// baseline (speedup 1.0000x reference)
#include <cuda_runtime.h>
#include <cuda_bf16.h>
#include <math.h>

// Problem constants
#define B_  4
#define N_  1024
#define C_  512
#define H_  8
#define HD_ 64
#define E_  16384
#define FF_ 2048   // 4*C

// ---------------- scratch (device globals; no allocations allowed) ----------
__device__ int   g_rel[B_ * N_ * N_];            // 16 MB  relation id per cell, -1 = none
__device__ float g_h  [B_ * N_ * C_];            // ln1 output
__device__ float g_q  [B_ * N_ * C_];
__device__ float g_k  [B_ * N_ * C_];
__device__ float g_v  [B_ * N_ * C_];
__device__ float g_scores[(size_t)B_ * H_ * N_ * N_];  // 128 MB
__device__ float g_att[B_ * N_ * C_];
__device__ float g_res[B_ * N_ * C_];            // x + attn (residual stream)
__device__ float g_h2 [B_ * N_ * C_];            // ln2 output
__device__ float g_mid[B_ * N_ * FF_];           // ffn hidden (32 MB)

// ---------------- bias map build --------------------------------------------
__global__ void init_rel_kernel(int* __restrict__ rel) {
    int idx = blockIdx.x * blockDim.x + threadIdx.x;
    int total = B_ * N_ * N_;
    for (int i = idx; i < total; i += gridDim.x * blockDim.x) rel[i] = -1;
}

__global__ void scatter_edges_kernel(const int* __restrict__ edge_index,
                                     const int* __restrict__ edge_type,
                                     int* __restrict__ rel) {
    int idx = blockIdx.x * blockDim.x + threadIdx.x;
    if (idx >= B_ * E_) return;
    int b = idx / E_;
    int e = idx - b * E_;
    int s = edge_index[b * 2 * E_ + e];          // edge_index[b,0,e]
    int t = edge_index[b * 2 * E_ + E_ + e];     // edge_index[b,1,e]
    int r = edge_type[b * E_ + e];
    if (s >= 0 && s < N_ && t >= 0 && t < N_) {
        atomicMax(&rel[b * N_ * N_ + s * N_ + t], r);
    }
}

// ---------------- layernorm --------------------------------------------------
__global__ __launch_bounds__(256)
void ln_kernel(const float* __restrict__ x, const float* __restrict__ gma,
               const float* __restrict__ bta, float* __restrict__ y) {
    int row = blockIdx.x;                 // B*N rows
    const float* xr = x + (size_t)row * C_;
    int t = threadIdx.x;
    float v0 = xr[t], v1 = xr[t + 256];
    __shared__ float sbuf[256];
    sbuf[t] = v0 + v1;
    __syncthreads();
    for (int o = 128; o > 0; o >>= 1) { if (t < o) sbuf[t] += sbuf[t + o]; __syncthreads(); }
    float mean = sbuf[0] * (1.0f / C_);
    __syncthreads();
    float d0 = v0 - mean, d1 = v1 - mean;
    sbuf[t] = d0 * d0 + d1 * d1;
    __syncthreads();
    for (int o = 128; o > 0; o >>= 1) { if (t < o) sbuf[t] += sbuf[t + o]; __syncthreads(); }
    float inv = rsqrtf(sbuf[0] * (1.0f / C_) + 1e-5f);
    float* yr = y + (size_t)row * C_;
    yr[t]       = d0 * inv * gma[t]       + bta[t];
    yr[t + 256] = d1 * inv * gma[t + 256] + bta[t + 256];
}

// ---------------- generic tiled GEMM: C = A[M,K] @ W[K,N] + bias, epilogue ---
// All dims are multiples of tile sizes in this problem (no bounds checks).
enum { EPI_BIAS = 0, EPI_GELU = 1, EPI_RES = 2 };

template <int EPI>
__global__ __launch_bounds__(256)
void gemm64(const float* __restrict__ A, const float* __restrict__ W,
            const float* __restrict__ bias, const float* __restrict__ res,
            float* __restrict__ Cout, int M, int Ncol, int K) {
    __shared__ float As[16][64];
    __shared__ float Ws[16][64];
    int tx = threadIdx.x, ty = threadIdx.y;
    int tid = ty * 16 + tx;
    int m0 = blockIdx.y * 64, n0 = blockIdx.x * 64;
    float acc[4][4] = {};
    for (int k0 = 0; k0 < K; k0 += 16) {
#pragma unroll
        for (int i = 0; i < 4; i++) {
            int e = tid + i * 256;
            int r = e >> 4, c = e & 15;
            As[c][r] = A[(size_t)(m0 + r) * K + k0 + c];
        }
#pragma unroll
        for (int i = 0; i < 4; i++) {
            int e = tid + i * 256;
            int r = e >> 6, c = e & 63;
            Ws[r][c] = W[(size_t)(k0 + r) * Ncol + n0 + c];
        }
        __syncthreads();
#pragma unroll
        for (int kk = 0; kk < 16; kk++) {
            float a[4], bv[4];
#pragma unroll
            for (int i = 0; i < 4; i++) a[i] = As[kk][ty * 4 + i];
#pragma unroll
            for (int j = 0; j < 4; j++) bv[j] = Ws[kk][tx * 4 + j];
#pragma unroll
            for (int i = 0; i < 4; i++)
#pragma unroll
                for (int j = 0; j < 4; j++) acc[i][j] += a[i] * bv[j];
        }
        __syncthreads();
    }
#pragma unroll
    for (int i = 0; i < 4; i++) {
        int row = m0 + ty * 4 + i;
#pragma unroll
        for (int j = 0; j < 4; j++) {
            int col = n0 + tx * 4 + j;
            float v = acc[i][j] + bias[col];
            if (EPI == EPI_GELU) v = 0.5f * v * (1.0f + erff(v * 0.70710678118654752f));
            if (EPI == EPI_RES)  v += res[(size_t)row * Ncol + col];
            Cout[(size_t)row * Ncol + col] = v;
        }
    }
}

// ---------------- attention scores: S = (Q Kt)*scale + bias -----------------
__global__ __launch_bounds__(256)
void attn_scores_kernel(const float* __restrict__ q, const float* __restrict__ k,
                        const int* __restrict__ rel, const float* __restrict__ table,
                        float* __restrict__ scores) {
    __shared__ float Qs[16][64];
    __shared__ float Ks[16][64];
    int bh = blockIdx.z;
    int b = bh >> 3, h = bh & 7;
    const float* Qb = q + (size_t)b * N_ * C_ + h * HD_;
    const float* Kb = k + (size_t)b * N_ * C_ + h * HD_;
    int tx = threadIdx.x, ty = threadIdx.y;
    int tid = ty * 16 + tx;
    int m0 = blockIdx.y * 64, n0 = blockIdx.x * 64;
    float acc[4][4] = {};
    for (int k0 = 0; k0 < HD_; k0 += 16) {
#pragma unroll
        for (int i = 0; i < 4; i++) {
            int e = tid + i * 256;
            int r = e >> 4, c = e & 15;
            Qs[c][r] = Qb[(size_t)(m0 + r) * C_ + k0 + c];
            Ks[c][r] = Kb[(size_t)(n0 + r) * C_ + k0 + c];
        }
        __syncthreads();
#pragma unroll
        for (int kk = 0; kk < 16; kk++) {
            float a[4], bv[4];
#pragma unroll
            for (int i = 0; i < 4; i++) a[i] = Qs[kk][ty * 4 + i];
#pragma unroll
            for (int j = 0; j < 4; j++) bv[j] = Ks[kk][tx * 4 + j];
#pragma unroll
            for (int i = 0; i < 4; i++)
#pragma unroll
                for (int j = 0; j < 4; j++) acc[i][j] += a[i] * bv[j];
        }
        __syncthreads();
    }
    const int* relb = rel + b * N_ * N_;
    float* sb = scores + (size_t)bh * N_ * N_;
#pragma unroll
    for (int i = 0; i < 4; i++) {
        int qi = m0 + ty * 4 + i;
#pragma unroll
        for (int j = 0; j < 4; j++) {
            int kj = n0 + tx * 4 + j;
            int rv = relb[qi * N_ + kj];
            float bias = (rv >= 0) ? table[rv * H_ + h] : 0.0f;
            sb[(size_t)qi * N_ + kj] = acc[i][j] * 0.125f + bias;  // HD^-0.5 = 0.125
        }
    }
}

// ---------------- softmax over last dim (row length N_) ---------------------
__global__ __launch_bounds__(256)
void softmax_kernel(float* __restrict__ s) {
    size_t row = blockIdx.x;
    float* p = s + row * (size_t)N_;
    int t = threadIdx.x;
    float v[4];
    float mx = -INFINITY;
#pragma unroll
    for (int i = 0; i < 4; i++) { v[i] = p[t + i * 256]; mx = fmaxf(mx, v[i]); }
    __shared__ float sbuf[256];
    sbuf[t] = mx;
    __syncthreads();
    for (int o = 128; o > 0; o >>= 1) { if (t < o) sbuf[t] = fmaxf(sbuf[t], sbuf[t + o]); __syncthreads(); }
    mx = sbuf[0];
    __syncthreads();
    float sum = 0.0f;
#pragma unroll
    for (int i = 0; i < 4; i++) { v[i] = expf(v[i] - mx); sum += v[i]; }
    sbuf[t] = sum;
    __syncthreads();
    for (int o = 128; o > 0; o >>= 1) { if (t < o) sbuf[t] += sbuf[t + o]; __syncthreads(); }
    float inv = 1.0f / sbuf[0];
#pragma unroll
    for (int i = 0; i < 4; i++) p[t + i * 256] = v[i] * inv;
}

// ---------------- P @ V  (per b,h: [1024x1024] @ [1024x64]) ------------------
__global__ __launch_bounds__(256)
void attn_pv_kernel(const float* __restrict__ scores, const float* __restrict__ v,
                    float* __restrict__ att) {
    __shared__ float Ps[16][64];
    __shared__ float Vs[16][64];
    int bh = blockIdx.y;
    int b = bh >> 3, h = bh & 7;
    const float* Pb = scores + (size_t)bh * N_ * N_;
    const float* Vb = v + (size_t)b * N_ * C_ + h * HD_;
    int tx = threadIdx.x, ty = threadIdx.y;
    int tid = ty * 16 + tx;
    int m0 = blockIdx.x * 64;
    float acc[4][4] = {};
    for (int k0 = 0; k0 < N_; k0 += 16) {
#pragma unroll
        for (int i = 0; i < 4; i++) {
            int e = tid + i * 256;
            int r = e >> 4, c = e & 15;
            Ps[c][r] = Pb[(size_t)(m0 + r) * N_ + k0 + c];
        }
#pragma unroll
        for (int i = 0; i < 4; i++) {
            int e = tid + i * 256;
            int r = e >> 6, c = e & 63;
            Vs[r][c] = Vb[(size_t)(k0 + r) * C_ + c];
        }
        __syncthreads();
#pragma unroll
        for (int kk = 0; kk < 16; kk++) {
            float a[4], bv[4];
#pragma unroll
            for (int i = 0; i < 4; i++) a[i] = Ps[kk][ty * 4 + i];
#pragma unroll
            for (int j = 0; j < 4; j++) bv[j] = Vs[kk][tx * 4 + j];
#pragma unroll
            for (int i = 0; i < 4; i++)
#pragma unroll
                for (int j = 0; j < 4; j++) acc[i][j] += a[i] * bv[j];
        }
        __syncthreads();
    }
#pragma unroll
    for (int i = 0; i < 4; i++) {
        int qi = m0 + ty * 4 + i;
#pragma unroll
        for (int j = 0; j < 4; j++) {
            int d = tx * 4 + j;
            att[(size_t)b * N_ * C_ + (size_t)qi * C_ + h * HD_ + d] = acc[i][j];
        }
    }
}

// ---------------- launch ------------------------------------------------------
extern "C" void kernel_launch(void* const* d_in, const int* in_sizes, int n_in,
                              void* d_out, int out_size) {
    const float* x        = (const float*)d_in[0];
    const int*   eidx     = (const int*)  d_in[1];
    const int*   etype    = (const int*)  d_in[2];
    const float* q_w      = (const float*)d_in[3];
    const float* q_b      = (const float*)d_in[4];
    const float* k_w      = (const float*)d_in[5];
    const float* k_b      = (const float*)d_in[6];
    const float* v_w      = (const float*)d_in[7];
    const float* v_b      = (const float*)d_in[8];
    const float* o_w      = (const float*)d_in[9];
    const float* o_b      = (const float*)d_in[10];
    const float* table    = (const float*)d_in[11];
    const float* ln1_g    = (const float*)d_in[12];
    const float* ln1_b    = (const float*)d_in[13];
    const float* ln2_g    = (const float*)d_in[14];
    const float* ln2_b    = (const float*)d_in[15];
    const float* f1_w     = (const float*)d_in[16];
    const float* f1_b     = (const float*)d_in[17];
    const float* f2_w     = (const float*)d_in[18];
    const float* f2_b     = (const float*)d_in[19];
    float* out = (float*)d_out;

    void *p_rel, *p_h, *p_q, *p_k, *p_v, *p_sc, *p_att, *p_res, *p_h2, *p_mid;
    cudaGetSymbolAddress(&p_rel, g_rel);
    cudaGetSymbolAddress(&p_h,   g_h);
    cudaGetSymbolAddress(&p_q,   g_q);
    cudaGetSymbolAddress(&p_k,   g_k);
    cudaGetSymbolAddress(&p_v,   g_v);
    cudaGetSymbolAddress(&p_sc,  g_scores);
    cudaGetSymbolAddress(&p_att, g_att);
    cudaGetSymbolAddress(&p_res, g_res);
    cudaGetSymbolAddress(&p_h2,  g_h2);
    cudaGetSymbolAddress(&p_mid, g_mid);

    dim3 tb(16, 16);
    const int rows = B_ * N_;                       // 4096

    // 1) relation map
    init_rel_kernel<<<2048, 256>>>((int*)p_rel);
    scatter_edges_kernel<<<(B_ * E_) / 256, 256>>>(eidx, etype, (int*)p_rel);

    // 2) LN1
    ln_kernel<<<rows, 256>>>(x, ln1_g, ln1_b, (float*)p_h);

    // 3) QKV projections
    gemm64<EPI_BIAS><<<dim3(C_ / 64, rows / 64), tb>>>((float*)p_h, q_w, q_b, nullptr, (float*)p_q, rows, C_, C_);
    gemm64<EPI_BIAS><<<dim3(C_ / 64, rows / 64), tb>>>((float*)p_h, k_w, k_b, nullptr, (float*)p_k, rows, C_, C_);
    gemm64<EPI_BIAS><<<dim3(C_ / 64, rows / 64), tb>>>((float*)p_h, v_w, v_b, nullptr, (float*)p_v, rows, C_, C_);

    // 4) scores + bias, softmax, PV
    attn_scores_kernel<<<dim3(N_ / 64, N_ / 64, B_ * H_), tb>>>((float*)p_q, (float*)p_k, (int*)p_rel, table, (float*)p_sc);
    softmax_kernel<<<B_ * H_ * N_, 256>>>((float*)p_sc);
    attn_pv_kernel<<<dim3(N_ / 64, B_ * H_), tb>>>((float*)p_sc, (float*)p_v, (float*)p_att);

    // 5) output projection + residual
    gemm64<EPI_RES><<<dim3(C_ / 64, rows / 64), tb>>>((float*)p_att, o_w, o_b, x, (float*)p_res, rows, C_, C_);

    // 6) LN2 + FFN
    ln_kernel<<<rows, 256>>>((float*)p_res, ln2_g, ln2_b, (float*)p_h2);
    gemm64<EPI_GELU><<<dim3(FF_ / 64, rows / 64), tb>>>((float*)p_h2, f1_w, f1_b, nullptr, (float*)p_mid, rows, FF_, C_);
    gemm64<EPI_RES><<<dim3(C_ / 64, rows / 64), tb>>>((float*)p_mid, f2_w, f2_b, (float*)p_res, out, rows, C_, FF_);
}

// round 2
// speedup vs baseline: 3.0483x; 3.0483x over previous
#include <cuda_runtime.h>
#include <cuda_bf16.h>
#include <math.h>
#include <stdint.h>

// Problem constants
#define B_  4
#define N_  1024
#define C_  512
#define H_  8
#define HD_ 64
#define E_  16384
#define FF_ 2048

// ---------------- scratch ----------------------------------------------------
__device__ int   g_rel[B_ * N_ * N_];
__device__ float g_h  [B_ * N_ * C_];
__device__ float g_q  [B_ * N_ * C_];
__device__ float g_k  [B_ * N_ * C_];
__device__ float g_v  [B_ * N_ * C_];
__device__ float g_kT [B_ * H_ * HD_ * N_];          // [bh][k][n]
__device__ float g_scores[(size_t)B_ * H_ * N_ * N_];
__device__ float g_att[B_ * N_ * C_];
__device__ float g_res[B_ * N_ * C_];
__device__ float g_h2 [B_ * N_ * C_];
__device__ float g_mid[B_ * N_ * FF_];

// ---------------- helpers -----------------------------------------------------
__device__ __forceinline__ float to_tf32(float x) {
    uint32_t u;
    asm("cvt.rna.tf32.f32 %0, %1;" : "=r"(u) : "f"(x));
    return __uint_as_float(u);
}

__device__ __forceinline__ void mma_tf32(float* c, const uint32_t* a, const uint32_t* b) {
    asm volatile(
        "mma.sync.aligned.m16n8k8.row.col.f32.tf32.tf32.f32 "
        "{%0,%1,%2,%3}, {%4,%5,%6,%7}, {%8,%9}, {%0,%1,%2,%3};\n"
        : "+f"(c[0]), "+f"(c[1]), "+f"(c[2]), "+f"(c[3])
        : "r"(a[0]), "r"(a[1]), "r"(a[2]), "r"(a[3]), "r"(b[0]), "r"(b[1]));
}

// ---------------- bias map build ----------------------------------------------
__global__ void init_rel_kernel(int* __restrict__ rel) {
    int idx = blockIdx.x * blockDim.x + threadIdx.x;
    int total = B_ * N_ * N_;
    for (int i = idx; i < total; i += gridDim.x * blockDim.x) rel[i] = -1;
}

__global__ void scatter_edges_kernel(const int* __restrict__ edge_index,
                                     const int* __restrict__ edge_type,
                                     int* __restrict__ rel) {
    int idx = blockIdx.x * blockDim.x + threadIdx.x;
    if (idx >= B_ * E_) return;
    int b = idx / E_;
    int e = idx - b * E_;
    int s = edge_index[b * 2 * E_ + e];
    int t = edge_index[b * 2 * E_ + E_ + e];
    int r = edge_type[b * E_ + e];
    if (s >= 0 && s < N_ && t >= 0 && t < N_) {
        atomicMax(&rel[b * N_ * N_ + s * N_ + t], r);
    }
}

// ---------------- layernorm ----------------------------------------------------
__global__ __launch_bounds__(256)
void ln_kernel(const float* __restrict__ x, const float* __restrict__ gma,
               const float* __restrict__ bta, float* __restrict__ y) {
    int row = blockIdx.x;
    const float* xr = x + (size_t)row * C_;
    int t = threadIdx.x;
    float v0 = xr[t], v1 = xr[t + 256];
    __shared__ float sbuf[256];
    sbuf[t] = v0 + v1;
    __syncthreads();
    for (int o = 128; o > 0; o >>= 1) { if (t < o) sbuf[t] += sbuf[t + o]; __syncthreads(); }
    float mean = sbuf[0] * (1.0f / C_);
    __syncthreads();
    float d0 = v0 - mean, d1 = v1 - mean;
    sbuf[t] = d0 * d0 + d1 * d1;
    __syncthreads();
    for (int o = 128; o > 0; o >>= 1) { if (t < o) sbuf[t] += sbuf[t + o]; __syncthreads(); }
    float inv = rsqrtf(sbuf[0] * (1.0f / C_) + 1e-5f);
    float* yr = y + (size_t)row * C_;
    yr[t]       = d0 * inv * gma[t]       + bta[t];
    yr[t + 256] = d1 * inv * gma[t + 256] + bta[t + 256];
}

// ---------------- K transpose: kT[bh][k][n] = K[b][n][h*64+k] -------------------
__global__ __launch_bounds__(256)
void transpose_k_kernel(const float* __restrict__ k, float* __restrict__ kT) {
    __shared__ float t[32][33];
    int bh = blockIdx.z;
    int b = bh >> 3, h = bh & 7;
    int n0 = blockIdx.x * 32, k0 = blockIdx.y * 32;
    int tx = threadIdx.x & 31, ty = threadIdx.x >> 5;
#pragma unroll
    for (int i = 0; i < 4; i++) {
        int n = n0 + ty + i * 8;
        t[ty + i * 8][tx] = k[((size_t)b * N_ + n) * C_ + h * HD_ + k0 + tx];
    }
    __syncthreads();
#pragma unroll
    for (int i = 0; i < 4; i++) {
        int kk = k0 + ty + i * 8;
        kT[((size_t)bh * HD_ + kk) * N_ + n0 + tx] = t[tx][ty + i * 8];
    }
}

// ---------------- unified TF32 tensor-core GEMM --------------------------------
// C[M,Ncol] = A[M,K](lda) @ B[K,Ncol](ldb) + epilogue. BM=128, BK=32, 8 warps.
enum { EPI_BIAS = 0, EPI_GELU = 1, EPI_RES = 2, EPI_SCORES = 3, EPI_PV = 4 };

template <int BN, int WARPS_M, int MI, int NI, int EPI>
__global__ __launch_bounds__(256, 2)
void mm_tf32(const float* __restrict__ Abase,
             const float* __restrict__ W0, const float* __restrict__ W1,
             const float* __restrict__ W2,
             const float* __restrict__ bi0, const float* __restrict__ bi1,
             const float* __restrict__ bi2,
             const float* __restrict__ res,
             const int* __restrict__ rel, const float* __restrict__ table,
             float* __restrict__ O0, float* __restrict__ O1, float* __restrict__ O2,
             int M, int Ncol, int K, int lda, int ldb, int ldc) {
    constexpr int BM = 128;
    constexpr int BK = 32;
    constexpr int WM = MI * 16;
    constexpr int WN = NI * 8;

    __shared__ float As[BM][BK + 4];      // stride 36: banks gid*4+tig, bijective
    __shared__ float Bs[BK][BN + 8];      // stride BN+8: banks tig*8+gid, bijective

    int tid  = threadIdx.x;
    int warp = tid >> 5, lane = tid & 31;
    int gid = lane >> 2, tig = lane & 3;
    int wm = warp % WARPS_M, wn = warp / WARPS_M;
    int m0 = blockIdx.y * BM, n0 = blockIdx.x * BN;

    // resolve per-z pointers
    const float* A;
    const float* Bm;
    const float* bias = nullptr;
    float* Co;
    int b_ = 0, h_ = 0;
    if (EPI == EPI_SCORES) {
        int bh = blockIdx.z; b_ = bh >> 3; h_ = bh & 7;
        A  = Abase + (size_t)b_ * N_ * C_ + h_ * HD_;
        Bm = W0 + (size_t)bh * HD_ * N_;
        Co = O0 + (size_t)bh * N_ * N_;
    } else if (EPI == EPI_PV) {
        int bh = blockIdx.z; b_ = bh >> 3; h_ = bh & 7;
        A  = Abase + (size_t)bh * N_ * N_;
        Bm = W0 + (size_t)b_ * N_ * C_ + h_ * HD_;
        Co = O0 + (size_t)b_ * N_ * C_ + h_ * HD_;
    } else {
        int z = blockIdx.z;
        A    = Abase;
        Bm   = (z == 0) ? W0 : ((z == 1) ? W1 : W2);
        bias = (z == 0) ? bi0 : ((z == 1) ? bi1 : bi2);
        Co   = (z == 0) ? O0 : ((z == 1) ? O1 : O2);
    }

    float acc[MI][NI][4] = {};

    for (int k0 = 0; k0 < K; k0 += BK) {
        // load A tile 128x32: 4 float4 per thread
#pragma unroll
        for (int i = 0; i < 4; i++) {
            int f = tid + i * 256;
            int r = f >> 3, c = (f & 7) << 2;
            float4 v = *(const float4*)&A[(size_t)(m0 + r) * lda + k0 + c];
            As[r][c + 0] = to_tf32(v.x);
            As[r][c + 1] = to_tf32(v.y);
            As[r][c + 2] = to_tf32(v.z);
            As[r][c + 3] = to_tf32(v.w);
        }
        // load B tile 32xBN
        constexpr int BF4 = (BK * BN) / (4 * 256);   // float4s per thread (4 or 2)
#pragma unroll
        for (int i = 0; i < BF4; i++) {
            int f = tid + i * 256;
            int r, c;
            if (BN == 128) { r = f >> 5; c = (f & 31) << 2; }
            else           { r = f >> 4; c = (f & 15) << 2; }
            float4 v = *(const float4*)&Bm[(size_t)(k0 + r) * ldb + n0 + c];
            Bs[r][c + 0] = to_tf32(v.x);
            Bs[r][c + 1] = to_tf32(v.y);
            Bs[r][c + 2] = to_tf32(v.z);
            Bs[r][c + 3] = to_tf32(v.w);
        }
        __syncthreads();

#pragma unroll
        for (int ks = 0; ks < 4; ks++) {
            int kb = ks * 8;
            uint32_t af[MI][4];
#pragma unroll
            for (int mi = 0; mi < MI; mi++) {
                int r = wm * WM + mi * 16 + gid;
                af[mi][0] = __float_as_uint(As[r][kb + tig]);
                af[mi][1] = __float_as_uint(As[r + 8][kb + tig]);
                af[mi][2] = __float_as_uint(As[r][kb + tig + 4]);
                af[mi][3] = __float_as_uint(As[r + 8][kb + tig + 4]);
            }
            uint32_t bf[NI][2];
#pragma unroll
            for (int ni = 0; ni < NI; ni++) {
                int cn = wn * WN + ni * 8 + gid;
                bf[ni][0] = __float_as_uint(Bs[kb + tig][cn]);
                bf[ni][1] = __float_as_uint(Bs[kb + tig + 4][cn]);
            }
#pragma unroll
            for (int mi = 0; mi < MI; mi++)
#pragma unroll
                for (int ni = 0; ni < NI; ni++)
                    mma_tf32(acc[mi][ni], af[mi], bf[ni]);
        }
        __syncthreads();
    }

    // epilogue
#pragma unroll
    for (int mi = 0; mi < MI; mi++) {
#pragma unroll
        for (int ni = 0; ni < NI; ni++) {
            int r = m0 + wm * WM + mi * 16 + gid;
            int c = n0 + wn * WN + ni * 8 + tig * 2;
#pragma unroll
            for (int e = 0; e < 4; e++) {
                int rr = r + (e >> 1) * 8;
                int cc = c + (e & 1);
                float v = acc[mi][ni][e];
                if (EPI == EPI_SCORES) {
                    int rv = rel[b_ * N_ * N_ + rr * N_ + cc];
                    float bb = (rv >= 0) ? table[rv * H_ + h_] : 0.0f;
                    v = v * 0.125f + bb;
                } else if (EPI != EPI_PV) {
                    v += bias[cc];
                    if (EPI == EPI_GELU) v = 0.5f * v * (1.0f + erff(v * 0.70710678118654752f));
                    if (EPI == EPI_RES)  v += res[(size_t)rr * ldc + cc];
                }
                Co[(size_t)rr * ldc + cc] = v;
            }
        }
    }
}

// ---------------- softmax -------------------------------------------------------
__global__ __launch_bounds__(256)
void softmax_kernel(float* __restrict__ s) {
    size_t row = blockIdx.x;
    float* p = s + row * (size_t)N_;
    int t = threadIdx.x;
    float v[4];
    float mx = -INFINITY;
#pragma unroll
    for (int i = 0; i < 4; i++) { v[i] = p[t + i * 256]; mx = fmaxf(mx, v[i]); }
    __shared__ float sbuf[256];
    sbuf[t] = mx;
    __syncthreads();
    for (int o = 128; o > 0; o >>= 1) { if (t < o) sbuf[t] = fmaxf(sbuf[t], sbuf[t + o]); __syncthreads(); }
    mx = sbuf[0];
    __syncthreads();
    float sum = 0.0f;
#pragma unroll
    for (int i = 0; i < 4; i++) { v[i] = expf(v[i] - mx); sum += v[i]; }
    sbuf[t] = sum;
    __syncthreads();
    for (int o = 128; o > 0; o >>= 1) { if (t < o) sbuf[t] += sbuf[t + o]; __syncthreads(); }
    float inv = 1.0f / sbuf[0];
#pragma unroll
    for (int i = 0; i < 4; i++) p[t + i * 256] = v[i] * inv;
}

// ---------------- launch ---------------------------------------------------------
extern "C" void kernel_launch(void* const* d_in, const int* in_sizes, int n_in,
                              void* d_out, int out_size) {
    const float* x     = (const float*)d_in[0];
    const int*   eidx  = (const int*)  d_in[1];
    const int*   etype = (const int*)  d_in[2];
    const float* q_w   = (const float*)d_in[3];
    const float* q_b   = (const float*)d_in[4];
    const float* k_w   = (const float*)d_in[5];
    const float* k_b   = (const float*)d_in[6];
    const float* v_w   = (const float*)d_in[7];
    const float* v_b   = (const float*)d_in[8];
    const float* o_w   = (const float*)d_in[9];
    const float* o_b   = (const float*)d_in[10];
    const float* table = (const float*)d_in[11];
    const float* ln1_g = (const float*)d_in[12];
    const float* ln1_b = (const float*)d_in[13];
    const float* ln2_g = (const float*)d_in[14];
    const float* ln2_b = (const float*)d_in[15];
    const float* f1_w  = (const float*)d_in[16];
    const float* f1_b  = (const float*)d_in[17];
    const float* f2_w  = (const float*)d_in[18];
    const float* f2_b  = (const float*)d_in[19];
    float* out = (float*)d_out;

    void *p_rel, *p_h, *p_q, *p_k, *p_v, *p_kT, *p_sc, *p_att, *p_res, *p_h2, *p_mid;
    cudaGetSymbolAddress(&p_rel, g_rel);
    cudaGetSymbolAddress(&p_h,   g_h);
    cudaGetSymbolAddress(&p_q,   g_q);
    cudaGetSymbolAddress(&p_k,   g_k);
    cudaGetSymbolAddress(&p_v,   g_v);
    cudaGetSymbolAddress(&p_kT,  g_kT);
    cudaGetSymbolAddress(&p_sc,  g_scores);
    cudaGetSymbolAddress(&p_att, g_att);
    cudaGetSymbolAddress(&p_res, g_res);
    cudaGetSymbolAddress(&p_h2,  g_h2);
    cudaGetSymbolAddress(&p_mid, g_mid);

    const int rows = B_ * N_;   // 4096
    float* fq  = (float*)p_q;  float* fk = (float*)p_k;  float* fv = (float*)p_v;
    float* fh  = (float*)p_h;  float* fkT = (float*)p_kT; float* fsc = (float*)p_sc;
    float* fatt = (float*)p_att; float* fres = (float*)p_res;
    float* fh2 = (float*)p_h2; float* fmid = (float*)p_mid;
    int* frel = (int*)p_rel;

    // 1) relation map
    init_rel_kernel<<<2048, 256>>>(frel);
    scatter_edges_kernel<<<(B_ * E_) / 256, 256>>>(eidx, etype, frel);

    // 2) LN1
    ln_kernel<<<rows, 256>>>(x, ln1_g, ln1_b, fh);

    // 3) fused QKV projections (z selects weight set)
    mm_tf32<128, 2, 4, 4, EPI_BIAS><<<dim3(C_ / 128, rows / 128, 3), 256>>>(
        fh, q_w, k_w, v_w, q_b, k_b, v_b, nullptr, nullptr, nullptr,
        fq, fk, fv, rows, C_, C_, C_, C_, C_);

    // 4) transpose K → [bh][k][n]
    transpose_k_kernel<<<dim3(N_ / 32, HD_ / 32, B_ * H_), 256>>>(fk, fkT);

    // 5) scores (QK^T * scale + rel bias), softmax, PV
    mm_tf32<128, 2, 4, 4, EPI_SCORES><<<dim3(N_ / 128, N_ / 128, B_ * H_), 256>>>(
        fq, fkT, nullptr, nullptr, nullptr, nullptr, nullptr, nullptr, frel, table,
        fsc, nullptr, nullptr, N_, N_, HD_, C_, N_, N_);
    softmax_kernel<<<B_ * H_ * N_, 256>>>(fsc);
    mm_tf32<64, 4, 2, 4, EPI_PV><<<dim3(1, N_ / 128, B_ * H_), 256>>>(
        fsc, fv, nullptr, nullptr, nullptr, nullptr, nullptr, nullptr, nullptr, nullptr,
        fatt, nullptr, nullptr, N_, HD_, N_, N_, C_, C_);

    // 6) output projection + residual(x)
    mm_tf32<128, 2, 4, 4, EPI_RES><<<dim3(C_ / 128, rows / 128, 1), 256>>>(
        fatt, o_w, nullptr, nullptr, o_b, nullptr, nullptr, x, nullptr, nullptr,
        fres, nullptr, nullptr, rows, C_, C_, C_, C_, C_);

    // 7) LN2 + FFN
    ln_kernel<<<rows, 256>>>(fres, ln2_g, ln2_b, fh2);
    mm_tf32<128, 2, 4, 4, EPI_GELU><<<dim3(FF_ / 128, rows / 128, 1), 256>>>(
        fh2, f1_w, nullptr, nullptr, f1_b, nullptr, nullptr, nullptr, nullptr, nullptr,
        fmid, nullptr, nullptr, rows, FF_, C_, C_, FF_, FF_);
    mm_tf32<128, 2, 4, 4, EPI_RES><<<dim3(C_ / 128, rows / 128, 1), 256>>>(
        fmid, f2_w, nullptr, nullptr, f2_b, nullptr, nullptr, fres, nullptr, nullptr,
        out, nullptr, nullptr, rows, C_, FF_, FF_, C_, C_);
}

// round 3
// speedup vs baseline: 3.9212x; 1.2864x over previous
#include <cuda_runtime.h>
#include <math.h>
#include <stdint.h>

#define B_  4
#define N_  1024
#define C_  512
#define H_  8
#define HD_ 64
#define E_  16384
#define FF_ 2048

// ---------------- scratch ----------------------------------------------------
__device__ int   g_rel[B_ * N_ * N_];
__device__ float g_h  [B_ * N_ * C_];
__device__ float g_q  [B_ * N_ * C_];
__device__ float g_k  [B_ * N_ * C_];
__device__ float g_v  [B_ * N_ * C_];
__device__ float g_vT [B_ * H_ * HD_ * N_];          // [bh][d][n]
__device__ float g_scores[(size_t)B_ * H_ * N_ * N_];
__device__ float g_att[B_ * N_ * C_];
__device__ float g_res[B_ * N_ * C_];
__device__ float g_h2 [B_ * N_ * C_];
__device__ float g_mid[B_ * N_ * FF_];
// transposed (n-major) + tf32-rounded weights
__device__ float g_wqT[C_ * C_];
__device__ float g_wkT[C_ * C_];
__device__ float g_wvT[C_ * C_];
__device__ float g_woT[C_ * C_];
__device__ float g_f1T[FF_ * C_];
__device__ float g_f2T[C_ * FF_];

// ---------------- helpers -----------------------------------------------------
__device__ __forceinline__ float to_tf32(float x) {
    uint32_t u;
    asm("cvt.rna.tf32.f32 %0, %1;" : "=r"(u) : "f"(x));
    return __uint_as_float(u);
}

__device__ __forceinline__ void mma_tf32(float* c, const uint32_t* a, const uint32_t* b) {
    asm volatile(
        "mma.sync.aligned.m16n8k8.row.col.f32.tf32.tf32.f32 "
        "{%0,%1,%2,%3}, {%4,%5,%6,%7}, {%8,%9}, {%0,%1,%2,%3};\n"
        : "+f"(c[0]), "+f"(c[1]), "+f"(c[2]), "+f"(c[3])
        : "r"(a[0]), "r"(a[1]), "r"(a[2]), "r"(a[3]), "r"(b[0]), "r"(b[1]));
}

__device__ __forceinline__ void ldsm4(uint32_t* r, uint32_t addr) {
    asm volatile("ldmatrix.sync.aligned.m8n8.x4.shared.b16 {%0,%1,%2,%3}, [%4];\n"
                 : "=r"(r[0]), "=r"(r[1]), "=r"(r[2]), "=r"(r[3]) : "r"(addr));
}

__device__ __forceinline__ void cp16(uint32_t dst, const void* src) {
    asm volatile("cp.async.cg.shared.global [%0], [%1], 16;\n" :: "r"(dst), "l"(src));
}
__device__ __forceinline__ void cp_commit() { asm volatile("cp.async.commit_group;\n"); }
template <int NMAX>
__device__ __forceinline__ void cp_wait() { asm volatile("cp.async.wait_group %0;\n" :: "n"(NMAX)); }

// ---------------- bias map build ----------------------------------------------
__global__ void init_rel_kernel(int* __restrict__ rel) {
    int idx = blockIdx.x * blockDim.x + threadIdx.x;
    int total = B_ * N_ * N_;
    for (int i = idx; i < total; i += gridDim.x * blockDim.x) rel[i] = -1;
}

__global__ void scatter_edges_kernel(const int* __restrict__ edge_index,
                                     const int* __restrict__ edge_type,
                                     int* __restrict__ rel) {
    int idx = blockIdx.x * blockDim.x + threadIdx.x;
    if (idx >= B_ * E_) return;
    int b = idx / E_;
    int e = idx - b * E_;
    int s = edge_index[b * 2 * E_ + e];
    int t = edge_index[b * 2 * E_ + E_ + e];
    int r = edge_type[b * E_ + e];
    if (s >= 0 && s < N_ && t >= 0 && t < N_) {
        atomicMax(&rel[b * N_ * N_ + s * N_ + t], r);
    }
}

// ---------------- layernorm (emits tf32-rounded output) -------------------------
__global__ __launch_bounds__(256)
void ln_kernel(const float* __restrict__ x, const float* __restrict__ gma,
               const float* __restrict__ bta, float* __restrict__ y) {
    int row = blockIdx.x;
    const float* xr = x + (size_t)row * C_;
    int t = threadIdx.x;
    float v0 = xr[t], v1 = xr[t + 256];
    __shared__ float sbuf[256];
    sbuf[t] = v0 + v1;
    __syncthreads();
    for (int o = 128; o > 0; o >>= 1) { if (t < o) sbuf[t] += sbuf[t + o]; __syncthreads(); }
    float mean = sbuf[0] * (1.0f / C_);
    __syncthreads();
    float d0 = v0 - mean, d1 = v1 - mean;
    sbuf[t] = d0 * d0 + d1 * d1;
    __syncthreads();
    for (int o = 128; o > 0; o >>= 1) { if (t < o) sbuf[t] += sbuf[t + o]; __syncthreads(); }
    float inv = rsqrtf(sbuf[0] * (1.0f / C_) + 1e-5f);
    float* yr = y + (size_t)row * C_;
    yr[t]       = to_tf32(d0 * inv * gma[t]       + bta[t]);
    yr[t + 256] = to_tf32(d1 * inv * gma[t + 256] + bta[t + 256]);
}

// ---------------- weight transpose + round: dst[N][K] = round(src[K][N]) --------
__global__ __launch_bounds__(256)
void transpose_w_kernel(const float* __restrict__ src, float* __restrict__ dst,
                        int R, int Ccols) {
    __shared__ float t[32][33];
    int r0 = blockIdx.y * 32, c0 = blockIdx.x * 32;
    int tx = threadIdx.x & 31, ty = threadIdx.x >> 5;
#pragma unroll
    for (int i = 0; i < 4; i++)
        t[ty + i * 8][tx] = src[(size_t)(r0 + ty + i * 8) * Ccols + c0 + tx];
    __syncthreads();
#pragma unroll
    for (int i = 0; i < 4; i++)
        dst[(size_t)(c0 + ty + i * 8) * R + r0 + tx] = to_tf32(t[tx][ty + i * 8]);
}

// ---------------- V transpose: vT[bh][d][n] = v[b][n][h*64+d] --------------------
__global__ __launch_bounds__(256)
void transpose_v_kernel(const float* __restrict__ v, float* __restrict__ vT) {
    __shared__ float t[32][33];
    int bh = blockIdx.z;
    int b = bh >> 3, h = bh & 7;
    int n0 = blockIdx.x * 32, d0 = blockIdx.y * 32;
    int tx = threadIdx.x & 31, ty = threadIdx.x >> 5;
#pragma unroll
    for (int i = 0; i < 4; i++)
        t[ty + i * 8][tx] = v[((size_t)b * N_ + n0 + ty + i * 8) * C_ + h * HD_ + d0 + tx];
    __syncthreads();
#pragma unroll
    for (int i = 0; i < 4; i++)
        vT[((size_t)bh * HD_ + d0 + ty + i * 8) * N_ + n0 + tx] = t[tx][ty + i * 8];
}

// ---------------- pipelined tf32 tensor-core GEMM --------------------------------
// C[M,*] = A[M,K](lda, k-major) @ B(n-major: B[n][k], ldb) + epilogue
enum { EPI_BIAS = 0, EPI_GELU = 1, EPI_RES = 2, EPI_SCORES = 3, EPI_PV = 4 };

template <int BN, int WARPS_M, int MI, int NI, int EPI>
__global__ __launch_bounds__(256, 2)
void mm_tc(const float* __restrict__ Abase,
           const float* __restrict__ W0, const float* __restrict__ W1,
           const float* __restrict__ W2,
           const float* __restrict__ bi0, const float* __restrict__ bi1,
           const float* __restrict__ bi2,
           const float* __restrict__ res,
           const int* __restrict__ rel, const float* __restrict__ table,
           float* __restrict__ O0, float* __restrict__ O1, float* __restrict__ O2,
           int K, int lda, int ldb, int ldc) {
    constexpr int BM = 128;
    constexpr int BK = 32;
    constexpr int WM = MI * 16;
    constexpr int WN = NI * 8;
    constexpr int AS = BM * 36;       // floats per A stage (stride 36)
    constexpr int BS = BN * 36;
    constexpr int STG = AS + BS;

    extern __shared__ float sm[];
    uint32_t sbase = (uint32_t)__cvta_generic_to_shared(sm);

    int tid = threadIdx.x;
    int warp = tid >> 5, lane = tid & 31;
    int gid = lane >> 2, tig = lane & 3;
    int wm = warp % WARPS_M, wn = warp / WARPS_M;
    int m0 = blockIdx.y * BM, n0 = blockIdx.x * BN;

    const float* A;
    const float* Bm;
    const float* bias = nullptr;
    float* Co;
    int b_ = 0, h_ = 0;
    if (EPI == EPI_SCORES) {
        int bh = blockIdx.z; b_ = bh >> 3; h_ = bh & 7;
        A  = Abase + (size_t)b_ * N_ * C_ + h_ * HD_;   // q rows m, k-dim 64
        Bm = W0    + (size_t)b_ * N_ * C_ + h_ * HD_;   // k rows n, k-dim 64 (n-major!)
        Co = O0    + (size_t)bh * N_ * N_;
    } else if (EPI == EPI_PV) {
        int bh = blockIdx.z; b_ = bh >> 3; h_ = bh & 7;
        A  = Abase + (size_t)bh * N_ * N_;              // probs
        Bm = W0    + (size_t)bh * HD_ * N_;             // vT [d][n-seq]
        Co = O0    + (size_t)b_ * N_ * C_ + h_ * HD_;
    } else {
        int z = blockIdx.z;
        A    = Abase;
        Bm   = (z == 0) ? W0 : ((z == 1) ? W1 : W2);
        bias = (z == 0) ? bi0 : ((z == 1) ? bi1 : bi2);
        Co   = (z == 0) ? O0 : ((z == 1) ? O1 : O2);
    }

    // ldmatrix per-lane byte offsets
    int li = lane >> 3;                                      // matrix index 0..3
    uint32_t a_off = ((((li & 1) * 8) + (lane & 7)) * 36 + (li >> 1) * 4) * 4;
    uint32_t b_off = ((((li >> 1) * 8) + (lane & 7)) * 36 + (li & 1) * 4) * 4;

    float acc[MI][NI][4] = {};

    auto load_tile = [&](int stage, int k0) {
        uint32_t ab = sbase + stage * (STG * 4);
#pragma unroll
        for (int i = 0; i < 4; i++) {
            int f = tid + i * 256;
            int r = f >> 3, c = (f & 7) << 2;
            cp16(ab + (r * 36 + c) * 4, A + (size_t)(m0 + r) * lda + k0 + c);
        }
        uint32_t bb = sbase + (stage * STG + AS) * 4;
#pragma unroll
        for (int i = 0; i < (BN * BK) / 1024; i++) {
            int f = tid + i * 256;
            int r = f >> 3, c = (f & 7) << 2;
            cp16(bb + (r * 36 + c) * 4, Bm + (size_t)(n0 + r) * ldb + k0 + c);
        }
    };

    int KT = K / BK;
    load_tile(0, 0);
    cp_commit();

    for (int kt = 0; kt < KT; kt++) {
        int cur = kt & 1;
        if (kt + 1 < KT) {
            load_tile(cur ^ 1, (kt + 1) * BK);
            cp_commit();
            cp_wait<1>();
        } else {
            cp_wait<0>();
        }
        __syncthreads();

        uint32_t a_s = sbase + cur * (STG * 4) + (wm * WM) * 36 * 4 + a_off;
        uint32_t b_s = sbase + (cur * STG + AS) * 4 + (wn * WN) * 36 * 4 + b_off;
#pragma unroll
        for (int ks = 0; ks < 4; ks++) {
            uint32_t af[MI][4];
#pragma unroll
            for (int mi = 0; mi < MI; mi++)
                ldsm4(af[mi], a_s + mi * (16 * 36 * 4) + ks * 32);
            uint32_t bf[NI / 2][4];
#pragma unroll
            for (int p = 0; p < NI / 2; p++)
                ldsm4(bf[p], b_s + p * (16 * 36 * 4) + ks * 32);
#pragma unroll
            for (int mi = 0; mi < MI; mi++)
#pragma unroll
                for (int ni = 0; ni < NI; ni++)
                    mma_tf32(acc[mi][ni], af[mi], &bf[ni >> 1][(ni & 1) * 2]);
        }
        __syncthreads();
    }

    // epilogue (float2 stores; GEMM-input consumers get tf32-rounded values)
#pragma unroll
    for (int mi = 0; mi < MI; mi++) {
#pragma unroll
        for (int ni = 0; ni < NI; ni++) {
            int r = m0 + wm * WM + mi * 16 + gid;
            int c = n0 + wn * WN + ni * 8 + tig * 2;
#pragma unroll
            for (int e2 = 0; e2 < 2; e2++) {
                int rr = r + e2 * 8;
                float v0 = acc[mi][ni][e2 * 2];
                float v1 = acc[mi][ni][e2 * 2 + 1];
                if (EPI == EPI_SCORES) {
                    int2 rv = *(const int2*)&rel[b_ * N_ * N_ + rr * N_ + c];
                    v0 = v0 * 0.125f + ((rv.x >= 0) ? table[rv.x * H_ + h_] : 0.0f);
                    v1 = v1 * 0.125f + ((rv.y >= 0) ? table[rv.y * H_ + h_] : 0.0f);
                } else if (EPI == EPI_PV) {
                    v0 = to_tf32(v0); v1 = to_tf32(v1);
                } else {
                    float2 bb = *(const float2*)&bias[c];
                    v0 += bb.x; v1 += bb.y;
                    if (EPI == EPI_GELU) {
                        v0 = to_tf32(0.5f * v0 * (1.0f + erff(v0 * 0.70710678118654752f)));
                        v1 = to_tf32(0.5f * v1 * (1.0f + erff(v1 * 0.70710678118654752f)));
                    }
                    if (EPI == EPI_RES) {
                        float2 rr2 = *(const float2*)&res[(size_t)rr * ldc + c];
                        v0 += rr2.x; v1 += rr2.y;
                    }
                    if (EPI == EPI_BIAS) { v0 = to_tf32(v0); v1 = to_tf32(v1); }
                }
                *(float2*)&Co[(size_t)rr * ldc + c] = make_float2(v0, v1);
            }
        }
    }
}

// ---------------- softmax (emits tf32-rounded probs) -----------------------------
__global__ __launch_bounds__(256)
void softmax_kernel(float* __restrict__ s) {
    size_t row = blockIdx.x;
    float* p = s + row * (size_t)N_;
    int t = threadIdx.x;
    float v[4];
    float mx = -INFINITY;
#pragma unroll
    for (int i = 0; i < 4; i++) { v[i] = p[t + i * 256]; mx = fmaxf(mx, v[i]); }
    __shared__ float sbuf[256];
    sbuf[t] = mx;
    __syncthreads();
    for (int o = 128; o > 0; o >>= 1) { if (t < o) sbuf[t] = fmaxf(sbuf[t], sbuf[t + o]); __syncthreads(); }
    mx = sbuf[0];
    __syncthreads();
    float sum = 0.0f;
#pragma unroll
    for (int i = 0; i < 4; i++) { v[i] = expf(v[i] - mx); sum += v[i]; }
    sbuf[t] = sum;
    __syncthreads();
    for (int o = 128; o > 0; o >>= 1) { if (t < o) sbuf[t] += sbuf[t + o]; __syncthreads(); }
    float inv = 1.0f / sbuf[0];
#pragma unroll
    for (int i = 0; i < 4; i++) p[t + i * 256] = to_tf32(v[i] * inv);
}

// ---------------- launch -----------------------------------------------------------
extern "C" void kernel_launch(void* const* d_in, const int* in_sizes, int n_in,
                              void* d_out, int out_size) {
    const float* x     = (const float*)d_in[0];
    const int*   eidx  = (const int*)  d_in[1];
    const int*   etype = (const int*)  d_in[2];
    const float* q_w   = (const float*)d_in[3];
    const float* q_b   = (const float*)d_in[4];
    const float* k_w   = (const float*)d_in[5];
    const float* k_b   = (const float*)d_in[6];
    const float* v_w   = (const float*)d_in[7];
    const float* v_b   = (const float*)d_in[8];
    const float* o_w   = (const float*)d_in[9];
    const float* o_b   = (const float*)d_in[10];
    const float* table = (const float*)d_in[11];
    const float* ln1_g = (const float*)d_in[12];
    const float* ln1_b = (const float*)d_in[13];
    const float* ln2_g = (const float*)d_in[14];
    const float* ln2_b = (const float*)d_in[15];
    const float* f1_w  = (const float*)d_in[16];
    const float* f1_b  = (const float*)d_in[17];
    const float* f2_w  = (const float*)d_in[18];
    const float* f2_b  = (const float*)d_in[19];
    float* out = (float*)d_out;

    void *p_rel, *p_h, *p_q, *p_k, *p_v, *p_vT, *p_sc, *p_att, *p_res, *p_h2, *p_mid;
    void *p_wq, *p_wk, *p_wv, *p_wo, *p_f1, *p_f2;
    cudaGetSymbolAddress(&p_rel, g_rel);
    cudaGetSymbolAddress(&p_h,   g_h);
    cudaGetSymbolAddress(&p_q,   g_q);
    cudaGetSymbolAddress(&p_k,   g_k);
    cudaGetSymbolAddress(&p_v,   g_v);
    cudaGetSymbolAddress(&p_vT,  g_vT);
    cudaGetSymbolAddress(&p_sc,  g_scores);
    cudaGetSymbolAddress(&p_att, g_att);
    cudaGetSymbolAddress(&p_res, g_res);
    cudaGetSymbolAddress(&p_h2,  g_h2);
    cudaGetSymbolAddress(&p_mid, g_mid);
    cudaGetSymbolAddress(&p_wq,  g_wqT);
    cudaGetSymbolAddress(&p_wk,  g_wkT);
    cudaGetSymbolAddress(&p_wv,  g_wvT);
    cudaGetSymbolAddress(&p_wo,  g_woT);
    cudaGetSymbolAddress(&p_f1,  g_f1T);
    cudaGetSymbolAddress(&p_f2,  g_f2T);

    const int SMEM_BIG   = 2 * (128 * 36 + 128 * 36) * 4;   // 73728
    const int SMEM_SMALL = 2 * (128 * 36 +  64 * 36) * 4;   // 55296
    cudaFuncSetAttribute(mm_tc<128, 2, 4, 4, EPI_BIAS>,   cudaFuncAttributeMaxDynamicSharedMemorySize, SMEM_BIG);
    cudaFuncSetAttribute(mm_tc<128, 2, 4, 4, EPI_SCORES>, cudaFuncAttributeMaxDynamicSharedMemorySize, SMEM_BIG);
    cudaFuncSetAttribute(mm_tc<128, 2, 4, 4, EPI_RES>,    cudaFuncAttributeMaxDynamicSharedMemorySize, SMEM_BIG);
    cudaFuncSetAttribute(mm_tc<128, 2, 4, 4, EPI_GELU>,   cudaFuncAttributeMaxDynamicSharedMemorySize, SMEM_BIG);
    cudaFuncSetAttribute(mm_tc< 64, 4, 2, 4, EPI_PV>,     cudaFuncAttributeMaxDynamicSharedMemorySize, SMEM_SMALL);

    const int rows = B_ * N_;
    float* fh  = (float*)p_h;  float* fq = (float*)p_q;  float* fk = (float*)p_k;
    float* fv  = (float*)p_v;  float* fvT = (float*)p_vT; float* fsc = (float*)p_sc;
    float* fatt = (float*)p_att; float* fres = (float*)p_res;
    float* fh2 = (float*)p_h2; float* fmid = (float*)p_mid;
    int* frel = (int*)p_rel;

    // 0) weight prep (transpose to n-major + tf32 round)
    transpose_w_kernel<<<dim3(C_ / 32, C_ / 32), 256>>>(q_w, (float*)p_wq, C_, C_);
    transpose_w_kernel<<<dim3(C_ / 32, C_ / 32), 256>>>(k_w, (float*)p_wk, C_, C_);
    transpose_w_kernel<<<dim3(C_ / 32, C_ / 32), 256>>>(v_w, (float*)p_wv, C_, C_);
    transpose_w_kernel<<<dim3(C_ / 32, C_ / 32), 256>>>(o_w, (float*)p_wo, C_, C_);
    transpose_w_kernel<<<dim3(FF_ / 32, C_ / 32), 256>>>(f1_w, (float*)p_f1, C_, FF_);
    transpose_w_kernel<<<dim3(C_ / 32, FF_ / 32), 256>>>(f2_w, (float*)p_f2, FF_, C_);

    // 1) relation map
    init_rel_kernel<<<2048, 256>>>(frel);
    scatter_edges_kernel<<<(B_ * E_) / 256, 256>>>(eidx, etype, frel);

    // 2) LN1
    ln_kernel<<<rows, 256>>>(x, ln1_g, ln1_b, fh);

    // 3) fused QKV
    mm_tc<128, 2, 4, 4, EPI_BIAS><<<dim3(C_ / 128, rows / 128, 3), 256, SMEM_BIG>>>(
        fh, (float*)p_wq, (float*)p_wk, (float*)p_wv, q_b, k_b, v_b, nullptr, nullptr, nullptr,
        fq, fk, fv, C_, C_, C_, C_);

    // 4) transpose V per head for PV
    transpose_v_kernel<<<dim3(N_ / 32, HD_ / 32, B_ * H_), 256>>>(fv, fvT);

    // 5) scores (K is already n-major as B!), softmax, PV
    mm_tc<128, 2, 4, 4, EPI_SCORES><<<dim3(N_ / 128, N_ / 128, B_ * H_), 256, SMEM_BIG>>>(
        fq, fk, nullptr, nullptr, nullptr, nullptr, nullptr, nullptr, frel, table,
        fsc, nullptr, nullptr, HD_, C_, C_, N_);
    softmax_kernel<<<B_ * H_ * N_, 256>>>(fsc);
    mm_tc<64, 4, 2, 4, EPI_PV><<<dim3(1, N_ / 128, B_ * H_), 256, SMEM_SMALL>>>(
        fsc, fvT, nullptr, nullptr, nullptr, nullptr, nullptr, nullptr, nullptr, nullptr,
        fatt, nullptr, nullptr, N_, N_, N_, C_);

    // 6) output projection + residual(x)
    mm_tc<128, 2, 4, 4, EPI_RES><<<dim3(C_ / 128, rows / 128, 1), 256, SMEM_BIG>>>(
        fatt, (float*)p_wo, nullptr, nullptr, o_b, nullptr, nullptr, x, nullptr, nullptr,
        fres, nullptr, nullptr, C_, C_, C_, C_);

    // 7) LN2 + FFN
    ln_kernel<<<rows, 256>>>(fres, ln2_g, ln2_b, fh2);
    mm_tc<128, 2, 4, 4, EPI_GELU><<<dim3(FF_ / 128, rows / 128, 1), 256, SMEM_BIG>>>(
        fh2, (float*)p_f1, nullptr, nullptr, f1_b, nullptr, nullptr, nullptr, nullptr, nullptr,
        fmid, nullptr, nullptr, C_, C_, C_, FF_);
    mm_tc<128, 2, 4, 4, EPI_RES><<<dim3(C_ / 128, rows / 128, 1), 256, SMEM_BIG>>>(
        fmid, (float*)p_f2, nullptr, nullptr, f2_b, nullptr, nullptr, fres, nullptr, nullptr,
        out, nullptr, nullptr, FF_, FF_, FF_, C_);
}

// round 4
// speedup vs baseline: 4.4928x; 1.1458x over previous
#include <cuda_runtime.h>
#include <math.h>
#include <stdint.h>

#define B_  4
#define N_  1024
#define C_  512
#define H_  8
#define HD_ 64
#define E_  16384
#define FF_ 2048

// ---------------- scratch ----------------------------------------------------
__device__ int   g_rel[B_ * N_ * N_];
__device__ float g_h  [B_ * N_ * C_];
__device__ float g_q  [B_ * N_ * C_];
__device__ float g_k  [B_ * N_ * C_];
__device__ float g_v  [B_ * N_ * C_];
__device__ float g_vT [B_ * H_ * HD_ * N_];          // [bh][d][n]
__device__ float g_att[B_ * N_ * C_];
__device__ float g_res[B_ * N_ * C_];
__device__ float g_h2 [B_ * N_ * C_];
__device__ float g_mid[B_ * N_ * FF_];
// transposed (n-major) + tf32-rounded weights
__device__ float g_wqT[C_ * C_];
__device__ float g_wkT[C_ * C_];
__device__ float g_wvT[C_ * C_];
__device__ float g_woT[C_ * C_];
__device__ float g_f1T[FF_ * C_];
__device__ float g_f2T[C_ * FF_];

// ---------------- helpers -----------------------------------------------------
__device__ __forceinline__ float to_tf32(float x) {
    uint32_t u;
    asm("cvt.rna.tf32.f32 %0, %1;" : "=r"(u) : "f"(x));
    return __uint_as_float(u);
}

__device__ __forceinline__ void mma_tf32(float* c, const uint32_t* a, const uint32_t* b) {
    asm volatile(
        "mma.sync.aligned.m16n8k8.row.col.f32.tf32.tf32.f32 "
        "{%0,%1,%2,%3}, {%4,%5,%6,%7}, {%8,%9}, {%0,%1,%2,%3};\n"
        : "+f"(c[0]), "+f"(c[1]), "+f"(c[2]), "+f"(c[3])
        : "r"(a[0]), "r"(a[1]), "r"(a[2]), "r"(a[3]), "r"(b[0]), "r"(b[1]));
}

__device__ __forceinline__ void ldsm4(uint32_t* r, uint32_t addr) {
    asm volatile("ldmatrix.sync.aligned.m8n8.x4.shared.b16 {%0,%1,%2,%3}, [%4];\n"
                 : "=r"(r[0]), "=r"(r[1]), "=r"(r[2]), "=r"(r[3]) : "r"(addr));
}

__device__ __forceinline__ void cp16(uint32_t dst, const void* src) {
    asm volatile("cp.async.cg.shared.global [%0], [%1], 16;\n" :: "r"(dst), "l"(src));
}
__device__ __forceinline__ void cp_commit() { asm volatile("cp.async.commit_group;\n"); }
template <int NMAX>
__device__ __forceinline__ void cp_wait() { asm volatile("cp.async.wait_group %0;\n" :: "n"(NMAX)); }

// ---------------- bias map build ----------------------------------------------
__global__ void init_rel_kernel(int* __restrict__ rel) {
    int idx = blockIdx.x * blockDim.x + threadIdx.x;
    int total = B_ * N_ * N_;
    for (int i = idx; i < total; i += gridDim.x * blockDim.x) rel[i] = -1;
}

__global__ void scatter_edges_kernel(const int* __restrict__ edge_index,
                                     const int* __restrict__ edge_type,
                                     int* __restrict__ rel) {
    int idx = blockIdx.x * blockDim.x + threadIdx.x;
    if (idx >= B_ * E_) return;
    int b = idx / E_;
    int e = idx - b * E_;
    int s = edge_index[b * 2 * E_ + e];
    int t = edge_index[b * 2 * E_ + E_ + e];
    int r = edge_type[b * E_ + e];
    if (s >= 0 && s < N_ && t >= 0 && t < N_) {
        atomicMax(&rel[b * N_ * N_ + s * N_ + t], r);
    }
}

// ---------------- layernorm (emits tf32-rounded output) -------------------------
__global__ __launch_bounds__(256)
void ln_kernel(const float* __restrict__ x, const float* __restrict__ gma,
               const float* __restrict__ bta, float* __restrict__ y) {
    int row = blockIdx.x;
    const float* xr = x + (size_t)row * C_;
    int t = threadIdx.x;
    float v0 = xr[t], v1 = xr[t + 256];
    __shared__ float sbuf[256];
    sbuf[t] = v0 + v1;
    __syncthreads();
    for (int o = 128; o > 0; o >>= 1) { if (t < o) sbuf[t] += sbuf[t + o]; __syncthreads(); }
    float mean = sbuf[0] * (1.0f / C_);
    __syncthreads();
    float d0 = v0 - mean, d1 = v1 - mean;
    sbuf[t] = d0 * d0 + d1 * d1;
    __syncthreads();
    for (int o = 128; o > 0; o >>= 1) { if (t < o) sbuf[t] += sbuf[t + o]; __syncthreads(); }
    float inv = rsqrtf(sbuf[0] * (1.0f / C_) + 1e-5f);
    float* yr = y + (size_t)row * C_;
    yr[t]       = to_tf32(d0 * inv * gma[t]       + bta[t]);
    yr[t + 256] = to_tf32(d1 * inv * gma[t + 256] + bta[t + 256]);
}

// ---------------- weight transpose + round ---------------------------------------
__global__ __launch_bounds__(256)
void transpose_w_kernel(const float* __restrict__ src, float* __restrict__ dst,
                        int R, int Ccols) {
    __shared__ float t[32][33];
    int r0 = blockIdx.y * 32, c0 = blockIdx.x * 32;
    int tx = threadIdx.x & 31, ty = threadIdx.x >> 5;
#pragma unroll
    for (int i = 0; i < 4; i++)
        t[ty + i * 8][tx] = src[(size_t)(r0 + ty + i * 8) * Ccols + c0 + tx];
    __syncthreads();
#pragma unroll
    for (int i = 0; i < 4; i++)
        dst[(size_t)(c0 + ty + i * 8) * R + r0 + tx] = to_tf32(t[tx][ty + i * 8]);
}

// ---------------- V transpose: vT[bh][d][n] ---------------------------------------
__global__ __launch_bounds__(256)
void transpose_v_kernel(const float* __restrict__ v, float* __restrict__ vT) {
    __shared__ float t[32][33];
    int bh = blockIdx.z;
    int b = bh >> 3, h = bh & 7;
    int n0 = blockIdx.x * 32, d0 = blockIdx.y * 32;
    int tx = threadIdx.x & 31, ty = threadIdx.x >> 5;
#pragma unroll
    for (int i = 0; i < 4; i++)
        t[ty + i * 8][tx] = v[((size_t)b * N_ + n0 + ty + i * 8) * C_ + h * HD_ + d0 + tx];
    __syncthreads();
#pragma unroll
    for (int i = 0; i < 4; i++)
        vT[((size_t)bh * HD_ + d0 + ty + i * 8) * N_ + n0 + tx] = t[tx][ty + i * 8];
}

// ---------------- pipelined tf32 GEMM (projections / FFN) -------------------------
enum { EPI_BIAS = 0, EPI_GELU = 1, EPI_RES = 2 };

template <int BN, int WARPS_M, int MI, int NI, int EPI>
__global__ __launch_bounds__(256, 2)
void mm_tc(const float* __restrict__ Abase,
           const float* __restrict__ W0, const float* __restrict__ W1,
           const float* __restrict__ W2,
           const float* __restrict__ bi0, const float* __restrict__ bi1,
           const float* __restrict__ bi2,
           const float* __restrict__ res,
           float* __restrict__ O0, float* __restrict__ O1, float* __restrict__ O2,
           int K, int lda, int ldb, int ldc) {
    constexpr int BM = 128;
    constexpr int BK = 32;
    constexpr int WM = MI * 16;
    constexpr int WN = NI * 8;
    constexpr int AS = BM * 36;
    constexpr int BS = BN * 36;
    constexpr int STG = AS + BS;

    extern __shared__ float sm[];
    uint32_t sbase = (uint32_t)__cvta_generic_to_shared(sm);

    int tid = threadIdx.x;
    int warp = tid >> 5, lane = tid & 31;
    int gid = lane >> 2, tig = lane & 3;
    int wm = warp % WARPS_M, wn = warp / WARPS_M;
    int m0 = blockIdx.y * BM, n0 = blockIdx.x * BN;

    int z = blockIdx.z;
    const float* A   = Abase;
    const float* Bm  = (z == 0) ? W0 : ((z == 1) ? W1 : W2);
    const float* bias = (z == 0) ? bi0 : ((z == 1) ? bi1 : bi2);
    float* Co        = (z == 0) ? O0 : ((z == 1) ? O1 : O2);

    int li = lane >> 3;
    uint32_t a_off = ((((li & 1) * 8) + (lane & 7)) * 36 + (li >> 1) * 4) * 4;
    uint32_t b_off = ((((li >> 1) * 8) + (lane & 7)) * 36 + (li & 1) * 4) * 4;

    float acc[MI][NI][4] = {};

    auto load_tile = [&](int stage, int k0) {
        uint32_t ab = sbase + stage * (STG * 4);
#pragma unroll
        for (int i = 0; i < 4; i++) {
            int f = tid + i * 256;
            int r = f >> 3, c = (f & 7) << 2;
            cp16(ab + (r * 36 + c) * 4, A + (size_t)(m0 + r) * lda + k0 + c);
        }
        uint32_t bb = sbase + (stage * STG + AS) * 4;
#pragma unroll
        for (int i = 0; i < (BN * BK) / 1024; i++) {
            int f = tid + i * 256;
            int r = f >> 3, c = (f & 7) << 2;
            cp16(bb + (r * 36 + c) * 4, Bm + (size_t)(n0 + r) * ldb + k0 + c);
        }
    };

    int KT = K / BK;
    load_tile(0, 0);
    cp_commit();

    for (int kt = 0; kt < KT; kt++) {
        int cur = kt & 1;
        if (kt + 1 < KT) {
            load_tile(cur ^ 1, (kt + 1) * BK);
            cp_commit();
            cp_wait<1>();
        } else {
            cp_wait<0>();
        }
        __syncthreads();

        uint32_t a_s = sbase + cur * (STG * 4) + (wm * WM) * 36 * 4 + a_off;
        uint32_t b_s = sbase + (cur * STG + AS) * 4 + (wn * WN) * 36 * 4 + b_off;
#pragma unroll
        for (int ks = 0; ks < 4; ks++) {
            uint32_t af[MI][4];
#pragma unroll
            for (int mi = 0; mi < MI; mi++)
                ldsm4(af[mi], a_s + mi * (16 * 36 * 4) + ks * 32);
            uint32_t bf[NI / 2][4];
#pragma unroll
            for (int p = 0; p < NI / 2; p++)
                ldsm4(bf[p], b_s + p * (16 * 36 * 4) + ks * 32);
#pragma unroll
            for (int mi = 0; mi < MI; mi++)
#pragma unroll
                for (int ni = 0; ni < NI; ni++)
                    mma_tf32(acc[mi][ni], af[mi], &bf[ni >> 1][(ni & 1) * 2]);
        }
        __syncthreads();
    }

#pragma unroll
    for (int mi = 0; mi < MI; mi++) {
#pragma unroll
        for (int ni = 0; ni < NI; ni++) {
            int r = m0 + wm * WM + mi * 16 + gid;
            int c = n0 + wn * WN + ni * 8 + tig * 2;
#pragma unroll
            for (int e2 = 0; e2 < 2; e2++) {
                int rr = r + e2 * 8;
                float v0 = acc[mi][ni][e2 * 2];
                float v1 = acc[mi][ni][e2 * 2 + 1];
                float2 bb = *(const float2*)&bias[c];
                v0 += bb.x; v1 += bb.y;
                if (EPI == EPI_GELU) {
                    v0 = to_tf32(0.5f * v0 * (1.0f + erff(v0 * 0.70710678118654752f)));
                    v1 = to_tf32(0.5f * v1 * (1.0f + erff(v1 * 0.70710678118654752f)));
                }
                if (EPI == EPI_RES) {
                    float2 rr2 = *(const float2*)&res[(size_t)rr * ldc + c];
                    v0 += rr2.x; v1 += rr2.y;
                }
                if (EPI == EPI_BIAS) { v0 = to_tf32(v0); v1 = to_tf32(v1); }
                *(float2*)&Co[(size_t)rr * ldc + c] = make_float2(v0, v1);
            }
        }
    }
}

// ---------------- fused flash attention -------------------------------------------
// grid (N/128, B*H). Q in regs, K/V double-buffered cp.async, S relayout via smem,
// online softmax, fp32 accumulator, rel-bias gathered in S epilogue.
#define SD 68                       // smem row stride (floats), odd in float4 units

__global__ __launch_bounds__(256, 1)
void flash_attn_kernel(const float* __restrict__ q, const float* __restrict__ k,
                       const float* __restrict__ vT, const int* __restrict__ rel,
                       const float* __restrict__ table, float* __restrict__ att) {
    extern __shared__ float sm[];
    float* S    = sm;                       // 128*SD
    float* mrow = sm + 128 * SD + 2 * 64 * SD * 2;  // after K,V stages
    float* lrow = mrow + 128;
    float* frow = lrow + 128;
    float* tbl  = frow + 128;

    uint32_t sb  = (uint32_t)__cvta_generic_to_shared(sm);
    uint32_t S_u = sb;
    uint32_t K_u = sb + 128 * SD * 4;
    uint32_t V_u = K_u + 2 * 64 * SD * 4;

    int tid = threadIdx.x;
    int warp = tid >> 5, lane = tid & 31;
    int gid = lane >> 2, tig = lane & 3;
    int wm = warp & 3, wn = warp >> 2;            // 4 x 2 warp grid
    int bh = blockIdx.y, b = bh >> 3, h = bh & 7;
    int m0 = blockIdx.x * 128;

    const float* Q  = q  + (size_t)b * N_ * C_ + h * HD_;
    const float* Kp = k  + (size_t)b * N_ * C_ + h * HD_;
    const float* Vt = vT + (size_t)bh * HD_ * N_;
    const int* relb = rel + b * N_ * N_;

    for (int i = tid; i < 128; i += 256) { mrow[i] = -INFINITY; lrow[i] = 0.0f; }
    if (tid < 8) tbl[tid] = table[tid * H_ + h];

    // stage Q tile into S buffer, then ldmatrix into registers
#pragma unroll
    for (int i = 0; i < 8; i++) {
        int f = tid + i * 256;
        int r = f >> 4, c = (f & 15) << 2;
        cp16(S_u + (r * SD + c) * 4, Q + (size_t)(m0 + r) * C_ + c);
    }
    cp_commit();
    cp_wait<0>();
    __syncthreads();

    int li = lane >> 3;
    uint32_t a_off = ((((li & 1) * 8) + (lane & 7)) * SD + (li >> 1) * 4) * 4;
    uint32_t b_off = ((((li >> 1) * 8) + (lane & 7)) * SD + (li & 1) * 4) * 4;

    uint32_t qf[8][2][4];
    {
        uint32_t qbase = S_u + (wm * 32) * SD * 4 + a_off;
#pragma unroll
        for (int ks = 0; ks < 8; ks++)
#pragma unroll
            for (int mi = 0; mi < 2; mi++)
                ldsm4(qf[ks][mi], qbase + mi * (16 * SD * 4) + ks * 32);
    }
    __syncthreads();   // S buffer free for reuse

    float acc_o[2][4][4] = {};

    auto load_kv = [&](int stage, int kn0) {
        uint32_t kb = K_u + stage * (64 * SD * 4);
        uint32_t vb = V_u + stage * (64 * SD * 4);
#pragma unroll
        for (int i = 0; i < 4; i++) {
            int f = tid + i * 256;
            int r = f >> 4, c = (f & 15) << 2;
            cp16(kb + (r * SD + c) * 4, Kp + (size_t)(kn0 + r) * C_ + c);
            cp16(vb + (r * SD + c) * 4, Vt + (size_t)r * N_ + kn0 + c);
        }
    };

    load_kv(0, 0);
    cp_commit();

    for (int kt = 0; kt < N_ / 64; kt++) {
        int cur = kt & 1;
        int kn0 = kt * 64;
        if (kt + 1 < N_ / 64) {
            load_kv(cur ^ 1, (kt + 1) * 64);
            cp_commit();
            cp_wait<1>();
        } else {
            cp_wait<0>();
        }
        __syncthreads();

        // S = Q K^T
        float acc_s[2][4][4] = {};
        {
            uint32_t kb = K_u + cur * (64 * SD * 4) + (wn * 32) * SD * 4 + b_off;
#pragma unroll
            for (int ks = 0; ks < 8; ks++) {
                uint32_t bf[2][4];
#pragma unroll
                for (int p = 0; p < 2; p++)
                    ldsm4(bf[p], kb + p * (16 * SD * 4) + ks * 32);
#pragma unroll
                for (int mi = 0; mi < 2; mi++)
#pragma unroll
                    for (int ni = 0; ni < 4; ni++)
                        mma_tf32(acc_s[mi][ni], qf[ks][mi], &bf[ni >> 1][(ni & 1) * 2]);
            }
        }

        // epilogue: scale + rel bias -> S smem (fp32 scores)
#pragma unroll
        for (int mi = 0; mi < 2; mi++) {
#pragma unroll
            for (int ni = 0; ni < 4; ni++) {
                int row = wm * 32 + mi * 16 + gid;
                int col = wn * 32 + ni * 8 + tig * 2;
#pragma unroll
                for (int e2 = 0; e2 < 2; e2++) {
                    int rr = row + e2 * 8;
                    int2 rv = *(const int2*)&relb[(size_t)(m0 + rr) * N_ + kn0 + col];
                    float v0 = acc_s[mi][ni][e2 * 2]     * 0.125f + ((rv.x >= 0) ? tbl[rv.x] : 0.0f);
                    float v1 = acc_s[mi][ni][e2 * 2 + 1] * 0.125f + ((rv.y >= 0) ? tbl[rv.y] : 0.0f);
                    *(float2*)&S[rr * SD + col] = make_float2(v0, v1);
                }
            }
        }
        __syncthreads();

        // online softmax: 2 threads per row, 32 cols each
        {
            int r = tid >> 1, half = tid & 1;
            float* Sr = S + r * SD + half * 32;
            float vbuf[32];
            float mx = -INFINITY;
#pragma unroll
            for (int i = 0; i < 8; i++) {
                float4 x = *(const float4*)&Sr[i * 4];
                vbuf[i * 4] = x.x; vbuf[i * 4 + 1] = x.y; vbuf[i * 4 + 2] = x.z; vbuf[i * 4 + 3] = x.w;
                mx = fmaxf(mx, fmaxf(fmaxf(x.x, x.y), fmaxf(x.z, x.w)));
            }
            mx = fmaxf(mx, __shfl_xor_sync(0xffffffffu, mx, 1));
            float om = mrow[r];
            float nm = fmaxf(om, mx);
            float fr = __expf(om - nm);
            float sum = 0.0f;
#pragma unroll
            for (int i = 0; i < 32; i++) {
                float p = __expf(vbuf[i] - nm);
                sum += p;
                vbuf[i] = to_tf32(p);
            }
#pragma unroll
            for (int i = 0; i < 8; i++)
                *(float4*)&Sr[i * 4] = make_float4(vbuf[i * 4], vbuf[i * 4 + 1], vbuf[i * 4 + 2], vbuf[i * 4 + 3]);
            sum += __shfl_xor_sync(0xffffffffu, sum, 1);
            if (half == 0) {
                mrow[r] = nm;
                lrow[r] = lrow[r] * fr + sum;
                frow[r] = fr;
            }
        }
        __syncthreads();

        // rescale accumulator
#pragma unroll
        for (int mi = 0; mi < 2; mi++) {
            int row = wm * 32 + mi * 16 + gid;
            float f0 = frow[row], f1 = frow[row + 8];
#pragma unroll
            for (int ni = 0; ni < 4; ni++) {
                acc_o[mi][ni][0] *= f0; acc_o[mi][ni][1] *= f0;
                acc_o[mi][ni][2] *= f1; acc_o[mi][ni][3] *= f1;
            }
        }

        // O += P V  (A = P from S smem, B = vT tile)
        {
            uint32_t pb = S_u + (wm * 32) * SD * 4 + a_off;
            uint32_t vb = V_u + cur * (64 * SD * 4) + (wn * 32) * SD * 4 + b_off;
#pragma unroll
            for (int ks = 0; ks < 8; ks++) {
                uint32_t af[2][4];
#pragma unroll
                for (int mi = 0; mi < 2; mi++)
                    ldsm4(af[mi], pb + mi * (16 * SD * 4) + ks * 32);
                uint32_t bf[2][4];
#pragma unroll
                for (int p = 0; p < 2; p++)
                    ldsm4(bf[p], vb + p * (16 * SD * 4) + ks * 32);
#pragma unroll
                for (int mi = 0; mi < 2; mi++)
#pragma unroll
                    for (int ni = 0; ni < 4; ni++)
                        mma_tf32(acc_o[mi][ni], af[mi], &bf[ni >> 1][(ni & 1) * 2]);
            }
        }
        __syncthreads();
    }

    // finalize: divide by l, round to tf32 (feeds O-proj GEMM), write att
#pragma unroll
    for (int mi = 0; mi < 2; mi++) {
#pragma unroll
        for (int ni = 0; ni < 4; ni++) {
            int row = wm * 32 + mi * 16 + gid;
            int col = wn * 32 + ni * 8 + tig * 2;
#pragma unroll
            for (int e2 = 0; e2 < 2; e2++) {
                int rr = row + e2 * 8;
                float inv = 1.0f / lrow[rr];
                float v0 = to_tf32(acc_o[mi][ni][e2 * 2] * inv);
                float v1 = to_tf32(acc_o[mi][ni][e2 * 2 + 1] * inv);
                *(float2*)&att[((size_t)b * N_ + m0 + rr) * C_ + h * HD_ + col] = make_float2(v0, v1);
            }
        }
    }
}

// ---------------- launch -----------------------------------------------------------
extern "C" void kernel_launch(void* const* d_in, const int* in_sizes, int n_in,
                              void* d_out, int out_size) {
    const float* x     = (const float*)d_in[0];
    const int*   eidx  = (const int*)  d_in[1];
    const int*   etype = (const int*)  d_in[2];
    const float* q_w   = (const float*)d_in[3];
    const float* q_b   = (const float*)d_in[4];
    const float* k_w   = (const float*)d_in[5];
    const float* k_b   = (const float*)d_in[6];
    const float* v_w   = (const float*)d_in[7];
    const float* v_b   = (const float*)d_in[8];
    const float* o_w   = (const float*)d_in[9];
    const float* o_b   = (const float*)d_in[10];
    const float* table = (const float*)d_in[11];
    const float* ln1_g = (const float*)d_in[12];
    const float* ln1_b = (const float*)d_in[13];
    const float* ln2_g = (const float*)d_in[14];
    const float* ln2_b = (const float*)d_in[15];
    const float* f1_w  = (const float*)d_in[16];
    const float* f1_b  = (const float*)d_in[17];
    const float* f2_w  = (const float*)d_in[18];
    const float* f2_b  = (const float*)d_in[19];
    float* out = (float*)d_out;

    void *p_rel, *p_h, *p_q, *p_k, *p_v, *p_vT, *p_att, *p_res, *p_h2, *p_mid;
    void *p_wq, *p_wk, *p_wv, *p_wo, *p_f1, *p_f2;
    cudaGetSymbolAddress(&p_rel, g_rel);
    cudaGetSymbolAddress(&p_h,   g_h);
    cudaGetSymbolAddress(&p_q,   g_q);
    cudaGetSymbolAddress(&p_k,   g_k);
    cudaGetSymbolAddress(&p_v,   g_v);
    cudaGetSymbolAddress(&p_vT,  g_vT);
    cudaGetSymbolAddress(&p_att, g_att);
    cudaGetSymbolAddress(&p_res, g_res);
    cudaGetSymbolAddress(&p_h2,  g_h2);
    cudaGetSymbolAddress(&p_mid, g_mid);
    cudaGetSymbolAddress(&p_wq,  g_wqT);
    cudaGetSymbolAddress(&p_wk,  g_wkT);
    cudaGetSymbolAddress(&p_wv,  g_wvT);
    cudaGetSymbolAddress(&p_wo,  g_woT);
    cudaGetSymbolAddress(&p_f1,  g_f1T);
    cudaGetSymbolAddress(&p_f2,  g_f2T);

    const int SMEM_BIG   = 2 * (128 * 36 + 128 * 36) * 4;   // 73728
    const int SMEM_FLASH = (128 * SD + 4 * 64 * SD + 3 * 128 + 8) * 4;
    cudaFuncSetAttribute(mm_tc<128, 2, 4, 4, EPI_BIAS>, cudaFuncAttributeMaxDynamicSharedMemorySize, SMEM_BIG);
    cudaFuncSetAttribute(mm_tc<128, 2, 4, 4, EPI_RES>,  cudaFuncAttributeMaxDynamicSharedMemorySize, SMEM_BIG);
    cudaFuncSetAttribute(mm_tc<128, 2, 4, 4, EPI_GELU>, cudaFuncAttributeMaxDynamicSharedMemorySize, SMEM_BIG);
    cudaFuncSetAttribute(flash_attn_kernel, cudaFuncAttributeMaxDynamicSharedMemorySize, SMEM_FLASH);

    const int rows = B_ * N_;
    float* fh  = (float*)p_h;  float* fq = (float*)p_q;  float* fk = (float*)p_k;
    float* fv  = (float*)p_v;  float* fvT = (float*)p_vT;
    float* fatt = (float*)p_att; float* fres = (float*)p_res;
    float* fh2 = (float*)p_h2; float* fmid = (float*)p_mid;
    int* frel = (int*)p_rel;

    // 0) weight prep
    transpose_w_kernel<<<dim3(C_ / 32, C_ / 32), 256>>>(q_w, (float*)p_wq, C_, C_);
    transpose_w_kernel<<<dim3(C_ / 32, C_ / 32), 256>>>(k_w, (float*)p_wk, C_, C_);
    transpose_w_kernel<<<dim3(C_ / 32, C_ / 32), 256>>>(v_w, (float*)p_wv, C_, C_);
    transpose_w_kernel<<<dim3(C_ / 32, C_ / 32), 256>>>(o_w, (float*)p_wo, C_, C_);
    transpose_w_kernel<<<dim3(FF_ / 32, C_ / 32), 256>>>(f1_w, (float*)p_f1, C_, FF_);
    transpose_w_kernel<<<dim3(C_ / 32, FF_ / 32), 256>>>(f2_w, (float*)p_f2, FF_, C_);

    // 1) relation map
    init_rel_kernel<<<2048, 256>>>(frel);
    scatter_edges_kernel<<<(B_ * E_) / 256, 256>>>(eidx, etype, frel);

    // 2) LN1
    ln_kernel<<<rows, 256>>>(x, ln1_g, ln1_b, fh);

    // 3) fused QKV
    mm_tc<128, 2, 4, 4, EPI_BIAS><<<dim3(C_ / 128, rows / 128, 3), 256, SMEM_BIG>>>(
        fh, (float*)p_wq, (float*)p_wk, (float*)p_wv, q_b, k_b, v_b, nullptr,
        fq, fk, fv, C_, C_, C_, C_);

    // 4) transpose V per head
    transpose_v_kernel<<<dim3(N_ / 32, HD_ / 32, B_ * H_), 256>>>(fv, fvT);

    // 5) fused attention (scores + bias + softmax + PV)
    flash_attn_kernel<<<dim3(N_ / 128, B_ * H_), 256, SMEM_FLASH>>>(
        fq, fk, fvT, frel, table, fatt);

    // 6) output projection + residual(x)
    mm_tc<128, 2, 4, 4, EPI_RES><<<dim3(C_ / 128, rows / 128, 1), 256, SMEM_BIG>>>(
        fatt, (float*)p_wo, nullptr, nullptr, o_b, nullptr, nullptr, x,
        fres, nullptr, nullptr, C_, C_, C_, C_);

    // 7) LN2 + FFN
    ln_kernel<<<rows, 256>>>(fres, ln2_g, ln2_b, fh2);
    mm_tc<128, 2, 4, 4, EPI_GELU><<<dim3(FF_ / 128, rows / 128, 1), 256, SMEM_BIG>>>(
        fh2, (float*)p_f1, nullptr, nullptr, f1_b, nullptr, nullptr, nullptr,
        fmid, nullptr, nullptr, C_, C_, C_, FF_);
    mm_tc<128, 2, 4, 4, EPI_RES><<<dim3(C_ / 128, rows / 128, 1), 256, SMEM_BIG>>>(
        fmid, (float*)p_f2, nullptr, nullptr, f2_b, nullptr, nullptr, fres,
        out, nullptr, nullptr, FF_, FF_, FF_, C_);
}

// round 5
// speedup vs baseline: 4.5641x; 1.0159x over previous
#include <cuda_runtime.h>
#include <math.h>
#include <stdint.h>

#define B_  4
#define N_  1024
#define C_  512
#define H_  8
#define HD_ 64
#define E_  16384
#define FF_ 2048

// ---------------- scratch ----------------------------------------------------
__device__ int     g_rel [B_ * N_ * N_];
__device__ uint8_t g_rel8[B_ * N_ * N_];             // rv+1, 0 = no edge
__device__ float g_h  [B_ * N_ * C_];
__device__ float g_q  [B_ * N_ * C_];
__device__ float g_k  [B_ * N_ * C_];
__device__ float g_v  [B_ * N_ * C_];
__device__ float g_vT [B_ * H_ * HD_ * N_];          // [bh][d][n]
__device__ float g_att[B_ * N_ * C_];
__device__ float g_res[B_ * N_ * C_];
__device__ float g_h2 [B_ * N_ * C_];
__device__ float g_mid[B_ * N_ * FF_];
// transposed (n-major) + tf32-rounded weights
__device__ float g_wqT[C_ * C_];
__device__ float g_wkT[C_ * C_];
__device__ float g_wvT[C_ * C_];
__device__ float g_woT[C_ * C_];
__device__ float g_f1T[FF_ * C_];
__device__ float g_f2T[C_ * FF_];

// ---------------- helpers -----------------------------------------------------
__device__ __forceinline__ float to_tf32(float x) {
    uint32_t u;
    asm("cvt.rna.tf32.f32 %0, %1;" : "=r"(u) : "f"(x));
    return __uint_as_float(u);
}

__device__ __forceinline__ void mma_tf32(float* c, const uint32_t* a, const uint32_t* b) {
    asm volatile(
        "mma.sync.aligned.m16n8k8.row.col.f32.tf32.tf32.f32 "
        "{%0,%1,%2,%3}, {%4,%5,%6,%7}, {%8,%9}, {%0,%1,%2,%3};\n"
        : "+f"(c[0]), "+f"(c[1]), "+f"(c[2]), "+f"(c[3])
        : "r"(a[0]), "r"(a[1]), "r"(a[2]), "r"(a[3]), "r"(b[0]), "r"(b[1]));
}

__device__ __forceinline__ void ldsm4(uint32_t* r, uint32_t addr) {
    asm volatile("ldmatrix.sync.aligned.m8n8.x4.shared.b16 {%0,%1,%2,%3}, [%4];\n"
                 : "=r"(r[0]), "=r"(r[1]), "=r"(r[2]), "=r"(r[3]) : "r"(addr));
}

__device__ __forceinline__ void cp16(uint32_t dst, const void* src) {
    asm volatile("cp.async.cg.shared.global [%0], [%1], 16;\n" :: "r"(dst), "l"(src));
}
__device__ __forceinline__ void cp_commit() { asm volatile("cp.async.commit_group;\n"); }
template <int NMAX>
__device__ __forceinline__ void cp_wait() { asm volatile("cp.async.wait_group %0;\n" :: "n"(NMAX)); }

// ---------------- batched weight transpose + tf32 round -------------------------
// block ranges: [0,1024) q/k/v/o (256 tiles each), [1024,2048) f1, [2048,3072) f2
__global__ __launch_bounds__(256)
void transpose_all_kernel(const float* __restrict__ q_w, const float* __restrict__ k_w,
                          const float* __restrict__ v_w, const float* __restrict__ o_w,
                          const float* __restrict__ f1_w, const float* __restrict__ f2_w) {
    __shared__ float t[32][33];
    int blk = blockIdx.x;
    const float* src;
    float* dst;
    int R, Ccols, ti;
    if (blk < 1024) {
        int m = blk >> 8; ti = blk & 255;
        src = (m == 0) ? q_w : (m == 1) ? k_w : (m == 2) ? v_w : o_w;
        dst = (m == 0) ? g_wqT : (m == 1) ? g_wkT : (m == 2) ? g_wvT : g_woT;
        R = C_; Ccols = C_;
    } else if (blk < 2048) {
        ti = blk - 1024; src = f1_w; dst = g_f1T; R = C_; Ccols = FF_;
    } else {
        ti = blk - 2048; src = f2_w; dst = g_f2T; R = FF_; Ccols = C_;
    }
    int ct = Ccols >> 5;
    int c0 = (ti % ct) * 32, r0 = (ti / ct) * 32;
    int tx = threadIdx.x & 31, ty = threadIdx.x >> 5;
#pragma unroll
    for (int i = 0; i < 4; i++)
        t[ty + i * 8][tx] = src[(size_t)(r0 + ty + i * 8) * Ccols + c0 + tx];
    __syncthreads();
#pragma unroll
    for (int i = 0; i < 4; i++)
        dst[(size_t)(c0 + ty + i * 8) * R + r0 + tx] = to_tf32(t[tx][ty + i * 8]);
}

// ---------------- bias map build ----------------------------------------------
__global__ void init_rel_kernel(int4* __restrict__ rel4) {
    int idx = blockIdx.x * blockDim.x + threadIdx.x;
    int total = (B_ * N_ * N_) / 4;
    int4 m1 = make_int4(-1, -1, -1, -1);
    for (int i = idx; i < total; i += gridDim.x * blockDim.x) rel4[i] = m1;
}

__global__ void scatter_edges_kernel(const int* __restrict__ edge_index,
                                     const int* __restrict__ edge_type,
                                     int* __restrict__ rel) {
    int idx = blockIdx.x * blockDim.x + threadIdx.x;
    if (idx >= B_ * E_) return;
    int b = idx / E_;
    int e = idx - b * E_;
    int s = edge_index[b * 2 * E_ + e];
    int t = edge_index[b * 2 * E_ + E_ + e];
    int r = edge_type[b * E_ + e];
    if (s >= 0 && s < N_ && t >= 0 && t < N_) {
        atomicMax(&rel[b * N_ * N_ + s * N_ + t], r);
    }
}

__global__ void pack_rel_kernel(const int4* __restrict__ rel4, uchar4* __restrict__ rel8) {
    int idx = blockIdx.x * blockDim.x + threadIdx.x;
    int total = (B_ * N_ * N_) / 4;
    for (int i = idx; i < total; i += gridDim.x * blockDim.x) {
        int4 v = rel4[i];
        rel8[i] = make_uchar4((uint8_t)(v.x + 1), (uint8_t)(v.y + 1),
                              (uint8_t)(v.z + 1), (uint8_t)(v.w + 1));
    }
}

// ---------------- layernorm (emits tf32-rounded output) -------------------------
__global__ __launch_bounds__(256)
void ln_kernel(const float* __restrict__ x, const float* __restrict__ gma,
               const float* __restrict__ bta, float* __restrict__ y) {
    int row = blockIdx.x;
    const float* xr = x + (size_t)row * C_;
    int t = threadIdx.x;
    float v0 = xr[t], v1 = xr[t + 256];
    __shared__ float sbuf[256];
    sbuf[t] = v0 + v1;
    __syncthreads();
    for (int o = 128; o > 0; o >>= 1) { if (t < o) sbuf[t] += sbuf[t + o]; __syncthreads(); }
    float mean = sbuf[0] * (1.0f / C_);
    __syncthreads();
    float d0 = v0 - mean, d1 = v1 - mean;
    sbuf[t] = d0 * d0 + d1 * d1;
    __syncthreads();
    for (int o = 128; o > 0; o >>= 1) { if (t < o) sbuf[t] += sbuf[t + o]; __syncthreads(); }
    float inv = rsqrtf(sbuf[0] * (1.0f / C_) + 1e-5f);
    float* yr = y + (size_t)row * C_;
    yr[t]       = to_tf32(d0 * inv * gma[t]       + bta[t]);
    yr[t + 256] = to_tf32(d1 * inv * gma[t + 256] + bta[t + 256]);
}

// ---------------- V transpose: vT[bh][d][n] ---------------------------------------
__global__ __launch_bounds__(256)
void transpose_v_kernel(const float* __restrict__ v, float* __restrict__ vT) {
    __shared__ float t[32][33];
    int bh = blockIdx.z;
    int b = bh >> 3, h = bh & 7;
    int n0 = blockIdx.x * 32, d0 = blockIdx.y * 32;
    int tx = threadIdx.x & 31, ty = threadIdx.x >> 5;
#pragma unroll
    for (int i = 0; i < 4; i++)
        t[ty + i * 8][tx] = v[((size_t)b * N_ + n0 + ty + i * 8) * C_ + h * HD_ + d0 + tx];
    __syncthreads();
#pragma unroll
    for (int i = 0; i < 4; i++)
        vT[((size_t)bh * HD_ + d0 + ty + i * 8) * N_ + n0 + tx] = t[tx][ty + i * 8];
}

// ---------------- pipelined tf32 GEMM (projections / FFN) -------------------------
enum { EPI_BIAS = 0, EPI_GELU = 1, EPI_RES = 2 };

template <int BN, int WARPS_M, int MI, int NI, int EPI>
__global__ __launch_bounds__(256, 2)
void mm_tc(const float* __restrict__ Abase,
           const float* __restrict__ W0, const float* __restrict__ W1,
           const float* __restrict__ W2,
           const float* __restrict__ bi0, const float* __restrict__ bi1,
           const float* __restrict__ bi2,
           const float* __restrict__ res,
           float* __restrict__ O0, float* __restrict__ O1, float* __restrict__ O2,
           int K, int lda, int ldb, int ldc) {
    constexpr int BM = 128;
    constexpr int BK = 32;
    constexpr int WM = MI * 16;
    constexpr int WN = NI * 8;
    constexpr int AS = BM * 36;
    constexpr int BS = BN * 36;
    constexpr int STG = AS + BS;

    extern __shared__ float sm[];
    uint32_t sbase = (uint32_t)__cvta_generic_to_shared(sm);

    int tid = threadIdx.x;
    int warp = tid >> 5, lane = tid & 31;
    int gid = lane >> 2, tig = lane & 3;
    int wm = warp % WARPS_M, wn = warp / WARPS_M;
    int m0 = blockIdx.y * BM, n0 = blockIdx.x * BN;

    int z = blockIdx.z;
    const float* A   = Abase;
    const float* Bm  = (z == 0) ? W0 : ((z == 1) ? W1 : W2);
    const float* bias = (z == 0) ? bi0 : ((z == 1) ? bi1 : bi2);
    float* Co        = (z == 0) ? O0 : ((z == 1) ? O1 : O2);

    int li = lane >> 3;
    uint32_t a_off = ((((li & 1) * 8) + (lane & 7)) * 36 + (li >> 1) * 4) * 4;
    uint32_t b_off = ((((li >> 1) * 8) + (lane & 7)) * 36 + (li & 1) * 4) * 4;

    float acc[MI][NI][4] = {};

    auto load_tile = [&](int stage, int k0) {
        uint32_t ab = sbase + stage * (STG * 4);
#pragma unroll
        for (int i = 0; i < 4; i++) {
            int f = tid + i * 256;
            int r = f >> 3, c = (f & 7) << 2;
            cp16(ab + (r * 36 + c) * 4, A + (size_t)(m0 + r) * lda + k0 + c);
        }
        uint32_t bb = sbase + (stage * STG + AS) * 4;
#pragma unroll
        for (int i = 0; i < (BN * BK) / 1024; i++) {
            int f = tid + i * 256;
            int r = f >> 3, c = (f & 7) << 2;
            cp16(bb + (r * 36 + c) * 4, Bm + (size_t)(n0 + r) * ldb + k0 + c);
        }
    };

    int KT = K / BK;
    load_tile(0, 0);
    cp_commit();

    for (int kt = 0; kt < KT; kt++) {
        int cur = kt & 1;
        if (kt + 1 < KT) {
            load_tile(cur ^ 1, (kt + 1) * BK);
            cp_commit();
            cp_wait<1>();
        } else {
            cp_wait<0>();
        }
        __syncthreads();

        uint32_t a_s = sbase + cur * (STG * 4) + (wm * WM) * 36 * 4 + a_off;
        uint32_t b_s = sbase + (cur * STG + AS) * 4 + (wn * WN) * 36 * 4 + b_off;
#pragma unroll
        for (int ks = 0; ks < 4; ks++) {
            uint32_t af[MI][4];
#pragma unroll
            for (int mi = 0; mi < MI; mi++)
                ldsm4(af[mi], a_s + mi * (16 * 36 * 4) + ks * 32);
            uint32_t bf[NI / 2][4];
#pragma unroll
            for (int p = 0; p < NI / 2; p++)
                ldsm4(bf[p], b_s + p * (16 * 36 * 4) + ks * 32);
#pragma unroll
            for (int mi = 0; mi < MI; mi++)
#pragma unroll
                for (int ni = 0; ni < NI; ni++)
                    mma_tf32(acc[mi][ni], af[mi], &bf[ni >> 1][(ni & 1) * 2]);
        }
        __syncthreads();
    }

#pragma unroll
    for (int mi = 0; mi < MI; mi++) {
#pragma unroll
        for (int ni = 0; ni < NI; ni++) {
            int r = m0 + wm * WM + mi * 16 + gid;
            int c = n0 + wn * WN + ni * 8 + tig * 2;
#pragma unroll
            for (int e2 = 0; e2 < 2; e2++) {
                int rr = r + e2 * 8;
                float v0 = acc[mi][ni][e2 * 2];
                float v1 = acc[mi][ni][e2 * 2 + 1];
                float2 bb = *(const float2*)&bias[c];
                v0 += bb.x; v1 += bb.y;
                if (EPI == EPI_GELU) {
                    v0 = to_tf32(0.5f * v0 * (1.0f + erff(v0 * 0.70710678118654752f)));
                    v1 = to_tf32(0.5f * v1 * (1.0f + erff(v1 * 0.70710678118654752f)));
                }
                if (EPI == EPI_RES) {
                    float2 rr2 = *(const float2*)&res[(size_t)rr * ldc + c];
                    v0 += rr2.x; v1 += rr2.y;
                }
                if (EPI == EPI_BIAS) { v0 = to_tf32(v0); v1 = to_tf32(v1); }
                *(float2*)&Co[(size_t)rr * ldc + c] = make_float2(v0, v1);
            }
        }
    }
}

// ---------------- fused flash attention (64-row q tiles, 2 CTAs/SM) ----------------
#define SD 68

__global__ __launch_bounds__(256, 2)
void flash_attn_kernel(const float* __restrict__ q, const float* __restrict__ k,
                       const float* __restrict__ vT, const uint8_t* __restrict__ rel8,
                       const float* __restrict__ table, float* __restrict__ att) {
    extern __shared__ float sm[];
    float* S    = sm;                         // 64*SD
    float* mrow = sm + 64 * SD + 2 * 64 * SD * 2;
    float* lrow = mrow + 64;
    float* frow = lrow + 64;
    float* tbl  = frow + 64;

    uint32_t sb  = (uint32_t)__cvta_generic_to_shared(sm);
    uint32_t S_u = sb;
    uint32_t K_u = sb + 64 * SD * 4;
    uint32_t V_u = K_u + 2 * 64 * SD * 4;

    int tid = threadIdx.x;
    int warp = tid >> 5, lane = tid & 31;
    int gid = lane >> 2, tig = lane & 3;
    int wm = warp & 3, wn = warp >> 2;            // 4 x 2 warps; warp tile 16x32
    int bh = blockIdx.y, b = bh >> 3, h = bh & 7;
    int m0 = blockIdx.x * 64;

    const float* Q  = q  + (size_t)b * N_ * C_ + h * HD_;
    const float* Kp = k  + (size_t)b * N_ * C_ + h * HD_;
    const float* Vt = vT + (size_t)bh * HD_ * N_;
    const uint8_t* relb = rel8 + (size_t)b * N_ * N_;

    if (tid < 64) { mrow[tid] = -INFINITY; lrow[tid] = 0.0f; }
    if (tid < 9)  tbl[tid] = (tid == 0) ? 0.0f : table[(tid - 1) * H_ + h];

    auto load_kv = [&](int stage, int kn0) {
        uint32_t kb = K_u + stage * (64 * SD * 4);
        uint32_t vb = V_u + stage * (64 * SD * 4);
#pragma unroll
        for (int i = 0; i < 4; i++) {
            int f = tid + i * 256;
            int r = f >> 4, c = (f & 15) << 2;
            cp16(kb + (r * SD + c) * 4, Kp + (size_t)(kn0 + r) * C_ + c);
            cp16(vb + (r * SD + c) * 4, Vt + (size_t)r * N_ + kn0 + c);
        }
    };

    // stage Q (64x64) into S buffer
#pragma unroll
    for (int i = 0; i < 4; i++) {
        int f = tid + i * 256;
        int r = f >> 4, c = (f & 15) << 2;
        cp16(S_u + (r * SD + c) * 4, Q + (size_t)(m0 + r) * C_ + c);
    }
    cp_commit();
    load_kv(0, 0);
    cp_commit();
    cp_wait<1>();            // Q group done; kv0 may still fly
    __syncthreads();

    int li = lane >> 3;
    uint32_t a_off = ((((li & 1) * 8) + (lane & 7)) * SD + (li >> 1) * 4) * 4;
    uint32_t b_off = ((((li >> 1) * 8) + (lane & 7)) * SD + (li & 1) * 4) * 4;

    uint32_t qf[8][4];
    {
        uint32_t qbase = S_u + (wm * 16) * SD * 4 + a_off;
#pragma unroll
        for (int ks = 0; ks < 8; ks++)
            ldsm4(qf[ks], qbase + ks * 32);
    }
    __syncthreads();   // S buffer free

    float acc_o[4][4] = {};

    for (int kt = 0; kt < N_ / 64; kt++) {
        int cur = kt & 1;
        int kn0 = kt * 64;
        if (kt + 1 < N_ / 64) {
            load_kv(cur ^ 1, (kt + 1) * 64);
            cp_commit();
            cp_wait<1>();
        } else {
            cp_wait<0>();
        }
        __syncthreads();

        // S = Q K^T
        float acc_s[4][4] = {};
        {
            uint32_t kb = K_u + cur * (64 * SD * 4) + (wn * 32) * SD * 4 + b_off;
#pragma unroll
            for (int ks = 0; ks < 8; ks++) {
                uint32_t bf[2][4];
#pragma unroll
                for (int p = 0; p < 2; p++)
                    ldsm4(bf[p], kb + p * (16 * SD * 4) + ks * 32);
#pragma unroll
                for (int ni = 0; ni < 4; ni++)
                    mma_tf32(acc_s[ni], qf[ks], &bf[ni >> 1][(ni & 1) * 2]);
            }
        }

        // epilogue: scale + rel bias -> S smem
#pragma unroll
        for (int ni = 0; ni < 4; ni++) {
            int row = wm * 16 + gid;
            int col = wn * 32 + ni * 8 + tig * 2;
#pragma unroll
            for (int e2 = 0; e2 < 2; e2++) {
                int rr = row + e2 * 8;
                uchar2 rv = *(const uchar2*)&relb[(size_t)(m0 + rr) * N_ + kn0 + col];
                float v0 = acc_s[ni][e2 * 2]     * 0.125f + tbl[rv.x];
                float v1 = acc_s[ni][e2 * 2 + 1] * 0.125f + tbl[rv.y];
                *(float2*)&S[rr * SD + col] = make_float2(v0, v1);
            }
        }
        __syncthreads();

        // online softmax: 4 threads per row, 16 cols each
        {
            int r = tid >> 2, quad = tid & 3;
            float* Sr = S + r * SD + quad * 16;
            float vbuf[16];
            float mx = -INFINITY;
#pragma unroll
            for (int i = 0; i < 4; i++) {
                float4 x = *(const float4*)&Sr[i * 4];
                vbuf[i * 4] = x.x; vbuf[i * 4 + 1] = x.y; vbuf[i * 4 + 2] = x.z; vbuf[i * 4 + 3] = x.w;
                mx = fmaxf(mx, fmaxf(fmaxf(x.x, x.y), fmaxf(x.z, x.w)));
            }
            mx = fmaxf(mx, __shfl_xor_sync(0xffffffffu, mx, 1));
            mx = fmaxf(mx, __shfl_xor_sync(0xffffffffu, mx, 2));
            float om = mrow[r];
            float nm = fmaxf(om, mx);
            float fr = __expf(om - nm);
            float sum = 0.0f;
#pragma unroll
            for (int i = 0; i < 16; i++) {
                float p = __expf(vbuf[i] - nm);
                sum += p;
                vbuf[i] = to_tf32(p);
            }
#pragma unroll
            for (int i = 0; i < 4; i++)
                *(float4*)&Sr[i * 4] = make_float4(vbuf[i * 4], vbuf[i * 4 + 1], vbuf[i * 4 + 2], vbuf[i * 4 + 3]);
            sum += __shfl_xor_sync(0xffffffffu, sum, 1);
            sum += __shfl_xor_sync(0xffffffffu, sum, 2);
            if (quad == 0) {
                mrow[r] = nm;
                lrow[r] = lrow[r] * fr + sum;
                frow[r] = fr;
            }
        }
        __syncthreads();

        // rescale accumulator
        {
            int row = wm * 16 + gid;
            float f0 = frow[row], f1 = frow[row + 8];
#pragma unroll
            for (int ni = 0; ni < 4; ni++) {
                acc_o[ni][0] *= f0; acc_o[ni][1] *= f0;
                acc_o[ni][2] *= f1; acc_o[ni][3] *= f1;
            }
        }

        // O += P V
        {
            uint32_t pb = S_u + (wm * 16) * SD * 4 + a_off;
            uint32_t vb = V_u + cur * (64 * SD * 4) + (wn * 32) * SD * 4 + b_off;
#pragma unroll
            for (int ks = 0; ks < 8; ks++) {
                uint32_t af[4];
                ldsm4(af, pb + ks * 32);
                uint32_t bf[2][4];
#pragma unroll
                for (int p = 0; p < 2; p++)
                    ldsm4(bf[p], vb + p * (16 * SD * 4) + ks * 32);
#pragma unroll
                for (int ni = 0; ni < 4; ni++)
                    mma_tf32(acc_o[ni], af, &bf[ni >> 1][(ni & 1) * 2]);
            }
        }
        __syncthreads();
    }

    // finalize
#pragma unroll
    for (int ni = 0; ni < 4; ni++) {
        int row = wm * 16 + gid;
        int col = wn * 32 + ni * 8 + tig * 2;
#pragma unroll
        for (int e2 = 0; e2 < 2; e2++) {
            int rr = row + e2 * 8;
            float inv = 1.0f / lrow[rr];
            float v0 = to_tf32(acc_o[ni][e2 * 2] * inv);
            float v1 = to_tf32(acc_o[ni][e2 * 2 + 1] * inv);
            *(float2*)&att[((size_t)b * N_ + m0 + rr) * C_ + h * HD_ + col] = make_float2(v0, v1);
        }
    }
}

// ---------------- launch -----------------------------------------------------------
extern "C" void kernel_launch(void* const* d_in, const int* in_sizes, int n_in,
                              void* d_out, int out_size) {
    const float* x     = (const float*)d_in[0];
    const int*   eidx  = (const int*)  d_in[1];
    const int*   etype = (const int*)  d_in[2];
    const float* q_w   = (const float*)d_in[3];
    const float* q_b   = (const float*)d_in[4];
    const float* k_w   = (const float*)d_in[5];
    const float* k_b   = (const float*)d_in[6];
    const float* v_w   = (const float*)d_in[7];
    const float* v_b   = (const float*)d_in[8];
    const float* o_w   = (const float*)d_in[9];
    const float* o_b   = (const float*)d_in[10];
    const float* table = (const float*)d_in[11];
    const float* ln1_g = (const float*)d_in[12];
    const float* ln1_b = (const float*)d_in[13];
    const float* ln2_g = (const float*)d_in[14];
    const float* ln2_b = (const float*)d_in[15];
    const float* f1_w  = (const float*)d_in[16];
    const float* f1_b  = (const float*)d_in[17];
    const float* f2_w  = (const float*)d_in[18];
    const float* f2_b  = (const float*)d_in[19];
    float* out = (float*)d_out;

    void *p_rel, *p_rel8, *p_h, *p_q, *p_k, *p_v, *p_vT, *p_att, *p_res, *p_h2, *p_mid;
    void *p_wq, *p_wk, *p_wv, *p_wo, *p_f1, *p_f2;
    cudaGetSymbolAddress(&p_rel,  g_rel);
    cudaGetSymbolAddress(&p_rel8, g_rel8);
    cudaGetSymbolAddress(&p_h,   g_h);
    cudaGetSymbolAddress(&p_q,   g_q);
    cudaGetSymbolAddress(&p_k,   g_k);
    cudaGetSymbolAddress(&p_v,   g_v);
    cudaGetSymbolAddress(&p_vT,  g_vT);
    cudaGetSymbolAddress(&p_att, g_att);
    cudaGetSymbolAddress(&p_res, g_res);
    cudaGetSymbolAddress(&p_h2,  g_h2);
    cudaGetSymbolAddress(&p_mid, g_mid);
    cudaGetSymbolAddress(&p_wq,  g_wqT);
    cudaGetSymbolAddress(&p_wk,  g_wkT);
    cudaGetSymbolAddress(&p_wv,  g_wvT);
    cudaGetSymbolAddress(&p_wo,  g_woT);
    cudaGetSymbolAddress(&p_f1,  g_f1T);
    cudaGetSymbolAddress(&p_f2,  g_f2T);

    const int SMEM_BIG   = 2 * (128 * 36 + 128 * 36) * 4;                  // 73728
    const int SMEM_FLASH = (64 * SD + 4 * 64 * SD + 3 * 64 + 16) * 4;      // ~88 KB
    cudaFuncSetAttribute(mm_tc<128, 2, 4, 4, EPI_BIAS>, cudaFuncAttributeMaxDynamicSharedMemorySize, SMEM_BIG);
    cudaFuncSetAttribute(mm_tc<128, 2, 4, 4, EPI_RES>,  cudaFuncAttributeMaxDynamicSharedMemorySize, SMEM_BIG);
    cudaFuncSetAttribute(mm_tc<128, 2, 4, 4, EPI_GELU>, cudaFuncAttributeMaxDynamicSharedMemorySize, SMEM_BIG);
    cudaFuncSetAttribute(flash_attn_kernel, cudaFuncAttributeMaxDynamicSharedMemorySize, SMEM_FLASH);

    const int rows = B_ * N_;
    float* fh  = (float*)p_h;  float* fq = (float*)p_q;  float* fk = (float*)p_k;
    float* fv  = (float*)p_v;  float* fvT = (float*)p_vT;
    float* fatt = (float*)p_att; float* fres = (float*)p_res;
    float* fh2 = (float*)p_h2; float* fmid = (float*)p_mid;
    int* frel = (int*)p_rel;

    // 1) batched weight prep
    transpose_all_kernel<<<3072, 256>>>(q_w, k_w, v_w, o_w, f1_w, f2_w);
    // 2-4) relation map + pack
    init_rel_kernel<<<2048, 256>>>((int4*)p_rel);
    scatter_edges_kernel<<<(B_ * E_) / 256, 256>>>(eidx, etype, frel);
    pack_rel_kernel<<<1024, 256>>>((const int4*)p_rel, (uchar4*)p_rel8);
    // 5) LN1
    ln_kernel<<<rows, 256>>>(x, ln1_g, ln1_b, fh);
    // 6) fused QKV  (6th launch -> ncu -s 5 profiles this)
    mm_tc<128, 2, 4, 4, EPI_BIAS><<<dim3(C_ / 128, rows / 128, 3), 256, SMEM_BIG>>>(
        fh, (float*)p_wq, (float*)p_wk, (float*)p_wv, q_b, k_b, v_b, nullptr,
        fq, fk, fv, C_, C_, C_, C_);
    // 7) transpose V per head
    transpose_v_kernel<<<dim3(N_ / 32, HD_ / 32, B_ * H_), 256>>>(fv, fvT);
    // 8) fused attention
    flash_attn_kernel<<<dim3(N_ / 64, B_ * H_), 256, SMEM_FLASH>>>(
        fq, fk, fvT, (const uint8_t*)p_rel8, table, fatt);
    // 9) output projection + residual(x)
    mm_tc<128, 2, 4, 4, EPI_RES><<<dim3(C_ / 128, rows / 128, 1), 256, SMEM_BIG>>>(
        fatt, (float*)p_wo, nullptr, nullptr, o_b, nullptr, nullptr, x,
        fres, nullptr, nullptr, C_, C_, C_, C_);
    // 10) LN2
    ln_kernel<<<rows, 256>>>(fres, ln2_g, ln2_b, fh2);
    // 11-12) FFN
    mm_tc<128, 2, 4, 4, EPI_GELU><<<dim3(FF_ / 128, rows / 128, 1), 256, SMEM_BIG>>>(
        fh2, (float*)p_f1, nullptr, nullptr, f1_b, nullptr, nullptr, nullptr,
        fmid, nullptr, nullptr, C_, C_, C_, FF_);
    mm_tc<128, 2, 4, 4, EPI_RES><<<dim3(C_ / 128, rows / 128, 1), 256, SMEM_BIG>>>(
        fmid, (float*)p_f2, nullptr, nullptr, f2_b, nullptr, nullptr, fres,
        out, nullptr, nullptr, FF_, FF_, FF_, C_);
}

// round 6
// speedup vs baseline: 7.1198x; 1.5600x over previous
#include <cuda_runtime.h>
#include <cuda_fp16.h>
#include <math.h>
#include <stdint.h>

#define B_  4
#define N_  1024
#define C_  512
#define H_  8
#define HD_ 64
#define E_  16384
#define FF_ 2048

// ---------------- scratch ----------------------------------------------------
__device__ int     g_rel [B_ * N_ * N_];
__device__ uint8_t g_rel8[B_ * N_ * N_];
__device__ __half g_h  [B_ * N_ * C_];
__device__ __half g_q  [B_ * N_ * C_];
__device__ __half g_k  [B_ * N_ * C_];
__device__ __half g_v  [B_ * N_ * C_];
__device__ __half g_vT [B_ * H_ * HD_ * N_];          // [bh][d][n]
__device__ __half g_att[B_ * N_ * C_];
__device__ float  g_res[B_ * N_ * C_];
__device__ __half g_h2 [B_ * N_ * C_];
__device__ __half g_mid[B_ * N_ * FF_];
// transposed (n-major) fp16 weights
__device__ __half g_wqT[C_ * C_];
__device__ __half g_wkT[C_ * C_];
__device__ __half g_wvT[C_ * C_];
__device__ __half g_woT[C_ * C_];
__device__ __half g_f1T[FF_ * C_];
__device__ __half g_f2T[C_ * FF_];

// ---------------- helpers -----------------------------------------------------
__device__ __forceinline__ void mma_f16(float* c, const uint32_t* a, const uint32_t* b) {
    asm volatile(
        "mma.sync.aligned.m16n8k16.row.col.f32.f16.f16.f32 "
        "{%0,%1,%2,%3}, {%4,%5,%6,%7}, {%8,%9}, {%0,%1,%2,%3};\n"
        : "+f"(c[0]), "+f"(c[1]), "+f"(c[2]), "+f"(c[3])
        : "r"(a[0]), "r"(a[1]), "r"(a[2]), "r"(a[3]), "r"(b[0]), "r"(b[1]));
}

__device__ __forceinline__ void ldsm4(uint32_t* r, uint32_t addr) {
    asm volatile("ldmatrix.sync.aligned.m8n8.x4.shared.b16 {%0,%1,%2,%3}, [%4];\n"
                 : "=r"(r[0]), "=r"(r[1]), "=r"(r[2]), "=r"(r[3]) : "r"(addr));
}

__device__ __forceinline__ void cp16(uint32_t dst, const void* src) {
    asm volatile("cp.async.cg.shared.global [%0], [%1], 16;\n" :: "r"(dst), "l"(src));
}
__device__ __forceinline__ void cp_commit() { asm volatile("cp.async.commit_group;\n"); }
template <int NMAX>
__device__ __forceinline__ void cp_wait() { asm volatile("cp.async.wait_group %0;\n" :: "n"(NMAX)); }

// ---------------- batched weight transpose + fp16 convert -----------------------
__global__ __launch_bounds__(256)
void transpose_all_kernel(const float* __restrict__ q_w, const float* __restrict__ k_w,
                          const float* __restrict__ v_w, const float* __restrict__ o_w,
                          const float* __restrict__ f1_w, const float* __restrict__ f2_w) {
    __shared__ float t[32][33];
    int blk = blockIdx.x;
    const float* src;
    __half* dst;
    int R, Ccols, ti;
    if (blk < 1024) {
        int m = blk >> 8; ti = blk & 255;
        src = (m == 0) ? q_w : (m == 1) ? k_w : (m == 2) ? v_w : o_w;
        dst = (m == 0) ? g_wqT : (m == 1) ? g_wkT : (m == 2) ? g_wvT : g_woT;
        R = C_; Ccols = C_;
    } else if (blk < 2048) {
        ti = blk - 1024; src = f1_w; dst = g_f1T; R = C_; Ccols = FF_;
    } else {
        ti = blk - 2048; src = f2_w; dst = g_f2T; R = FF_; Ccols = C_;
    }
    int ct = Ccols >> 5;
    int c0 = (ti % ct) * 32, r0 = (ti / ct) * 32;
    int tx = threadIdx.x & 31, ty = threadIdx.x >> 5;
#pragma unroll
    for (int i = 0; i < 4; i++)
        t[ty + i * 8][tx] = src[(size_t)(r0 + ty + i * 8) * Ccols + c0 + tx];
    __syncthreads();
#pragma unroll
    for (int i = 0; i < 4; i++)
        dst[(size_t)(c0 + ty + i * 8) * R + r0 + tx] = __float2half_rn(t[tx][ty + i * 8]);
}

// ---------------- bias map build ----------------------------------------------
__global__ void init_rel_kernel(int4* __restrict__ rel4) {
    int idx = blockIdx.x * blockDim.x + threadIdx.x;
    int total = (B_ * N_ * N_) / 4;
    int4 m1 = make_int4(-1, -1, -1, -1);
    for (int i = idx; i < total; i += gridDim.x * blockDim.x) rel4[i] = m1;
}

__global__ void scatter_edges_kernel(const int* __restrict__ edge_index,
                                     const int* __restrict__ edge_type,
                                     int* __restrict__ rel) {
    int idx = blockIdx.x * blockDim.x + threadIdx.x;
    if (idx >= B_ * E_) return;
    int b = idx / E_;
    int e = idx - b * E_;
    int s = edge_index[b * 2 * E_ + e];
    int t = edge_index[b * 2 * E_ + E_ + e];
    int r = edge_type[b * E_ + e];
    if (s >= 0 && s < N_ && t >= 0 && t < N_) {
        atomicMax(&rel[b * N_ * N_ + s * N_ + t], r);
    }
}

__global__ void pack_rel_kernel(const int4* __restrict__ rel4, uchar4* __restrict__ rel8) {
    int idx = blockIdx.x * blockDim.x + threadIdx.x;
    int total = (B_ * N_ * N_) / 4;
    for (int i = idx; i < total; i += gridDim.x * blockDim.x) {
        int4 v = rel4[i];
        rel8[i] = make_uchar4((uint8_t)(v.x + 1), (uint8_t)(v.y + 1),
                              (uint8_t)(v.z + 1), (uint8_t)(v.w + 1));
    }
}

// ---------------- layernorm (fp32 in, fp16 out) ---------------------------------
__global__ __launch_bounds__(256)
void ln_kernel(const float* __restrict__ x, const float* __restrict__ gma,
               const float* __restrict__ bta, __half* __restrict__ y) {
    int row = blockIdx.x;
    const float* xr = x + (size_t)row * C_;
    int t = threadIdx.x;
    float2 xv = *(const float2*)&xr[t * 2];
    __shared__ float sbuf[256];
    sbuf[t] = xv.x + xv.y;
    __syncthreads();
    for (int o = 128; o > 0; o >>= 1) { if (t < o) sbuf[t] += sbuf[t + o]; __syncthreads(); }
    float mean = sbuf[0] * (1.0f / C_);
    __syncthreads();
    float d0 = xv.x - mean, d1 = xv.y - mean;
    sbuf[t] = d0 * d0 + d1 * d1;
    __syncthreads();
    for (int o = 128; o > 0; o >>= 1) { if (t < o) sbuf[t] += sbuf[t + o]; __syncthreads(); }
    float inv = rsqrtf(sbuf[0] * (1.0f / C_) + 1e-5f);
    float2 g = *(const float2*)&gma[t * 2];
    float2 bb = *(const float2*)&bta[t * 2];
    *(__half2*)&y[(size_t)row * C_ + t * 2] =
        __floats2half2_rn(d0 * inv * g.x + bb.x, d1 * inv * g.y + bb.y);
}

// ---------------- V transpose (fp16) ----------------------------------------------
__global__ __launch_bounds__(256)
void transpose_v_kernel(const __half* __restrict__ v, __half* __restrict__ vT) {
    __shared__ __half t[32][34];
    int bh = blockIdx.z;
    int b = bh >> 3, h = bh & 7;
    int n0 = blockIdx.x * 32, d0 = blockIdx.y * 32;
    int tx = threadIdx.x & 31, ty = threadIdx.x >> 5;
#pragma unroll
    for (int i = 0; i < 4; i++)
        t[ty + i * 8][tx] = v[((size_t)b * N_ + n0 + ty + i * 8) * C_ + h * HD_ + d0 + tx];
    __syncthreads();
#pragma unroll
    for (int i = 0; i < 4; i++)
        vT[((size_t)bh * HD_ + d0 + ty + i * 8) * N_ + n0 + tx] = t[tx][ty + i * 8];
}

// ---------------- pipelined fp16 GEMM (projections / FFN) -------------------------
// C[M,*] = A[M,K] @ B[n][k] + epilogue.  BM=128, BN=128, BK=32 halves, 8 warps.
enum { EPI_BIAS = 0, EPI_GELU = 1, EPI_RES = 2 };
#define WST 40   // smem row stride in halves (80 B: conflict-free for ldmatrix)

template <int EPI>
__global__ __launch_bounds__(256, 2)
void mm_tc(const __half* __restrict__ Abase,
           const __half* __restrict__ W0, const __half* __restrict__ W1,
           const __half* __restrict__ W2,
           const float* __restrict__ bi0, const float* __restrict__ bi1,
           const float* __restrict__ bi2,
           const float* __restrict__ res,
           void* __restrict__ O0, void* __restrict__ O1, void* __restrict__ O2,
           int K, int lda, int ldb, int ldc) {
    constexpr int BM = 128, BN = 128, BK = 32;
    constexpr int MI = 4, NI = 4, WARPS_M = 2;
    constexpr int WM = MI * 16, WN = NI * 8;
    constexpr int AS_B = BM * WST * 2;          // bytes per A stage
    constexpr int STG_B = AS_B + BN * WST * 2;  // bytes per stage

    extern __shared__ char smc[];
    uint32_t sbase = (uint32_t)__cvta_generic_to_shared(smc);

    int tid = threadIdx.x;
    int warp = tid >> 5, lane = tid & 31;
    int gid = lane >> 2, tig = lane & 3;
    int wm = warp % WARPS_M, wn = warp / WARPS_M;
    int m0 = blockIdx.y * BM, n0 = blockIdx.x * BN;

    int z = blockIdx.z;
    const __half* A   = Abase;
    const __half* Bm  = (z == 0) ? W0 : ((z == 1) ? W1 : W2);
    const float* bias = (z == 0) ? bi0 : ((z == 1) ? bi1 : bi2);
    void* Co          = (z == 0) ? O0 : ((z == 1) ? O1 : O2);

    int li = lane >> 3;
    uint32_t a_off = ((((li & 1) * 8) + (lane & 7)) * WST + (li >> 1) * 8) * 2;
    uint32_t b_off = ((((li >> 1) * 8) + (lane & 7)) * WST + (li & 1) * 8) * 2;

    float acc[MI][NI][4] = {};

    auto load_tile = [&](int stage, int k0) {
        uint32_t ab = sbase + stage * STG_B;
#pragma unroll
        for (int i = 0; i < 2; i++) {
            int f = tid + i * 256;
            int r = f >> 2, c = (f & 3) << 3;           // 4 x 16B chunks per row
            cp16(ab + (r * WST + c) * 2, A + (size_t)(m0 + r) * lda + k0 + c);
        }
        uint32_t bb = sbase + stage * STG_B + AS_B;
#pragma unroll
        for (int i = 0; i < 2; i++) {
            int f = tid + i * 256;
            int r = f >> 2, c = (f & 3) << 3;
            cp16(bb + (r * WST + c) * 2, Bm + (size_t)(n0 + r) * ldb + k0 + c);
        }
    };

    int KT = K / BK;
    load_tile(0, 0);
    cp_commit();

    for (int kt = 0; kt < KT; kt++) {
        int cur = kt & 1;
        if (kt + 1 < KT) {
            load_tile(cur ^ 1, (kt + 1) * BK);
            cp_commit();
            cp_wait<1>();
        } else {
            cp_wait<0>();
        }
        __syncthreads();

        uint32_t a_s = sbase + cur * STG_B + (wm * WM) * WST * 2 + a_off;
        uint32_t b_s = sbase + cur * STG_B + AS_B + (wn * WN) * WST * 2 + b_off;
#pragma unroll
        for (int ks = 0; ks < 2; ks++) {                 // 2 x k16 per BK=32
            uint32_t af[MI][4];
#pragma unroll
            for (int mi = 0; mi < MI; mi++)
                ldsm4(af[mi], a_s + mi * (16 * WST * 2) + ks * 32);
            uint32_t bf[NI / 2][4];
#pragma unroll
            for (int p = 0; p < NI / 2; p++)
                ldsm4(bf[p], b_s + p * (16 * WST * 2) + ks * 32);
#pragma unroll
            for (int mi = 0; mi < MI; mi++)
#pragma unroll
                for (int ni = 0; ni < NI; ni++)
                    mma_f16(acc[mi][ni], af[mi], &bf[ni >> 1][(ni & 1) * 2]);
        }
        __syncthreads();
    }

#pragma unroll
    for (int mi = 0; mi < MI; mi++) {
#pragma unroll
        for (int ni = 0; ni < NI; ni++) {
            int r = m0 + wm * WM + mi * 16 + gid;
            int c = n0 + wn * WN + ni * 8 + tig * 2;
#pragma unroll
            for (int e2 = 0; e2 < 2; e2++) {
                int rr = r + e2 * 8;
                float v0 = acc[mi][ni][e2 * 2];
                float v1 = acc[mi][ni][e2 * 2 + 1];
                float2 bb = *(const float2*)&bias[c];
                v0 += bb.x; v1 += bb.y;
                if (EPI == EPI_GELU) {
                    v0 = 0.5f * v0 * (1.0f + erff(v0 * 0.70710678118654752f));
                    v1 = 0.5f * v1 * (1.0f + erff(v1 * 0.70710678118654752f));
                }
                if (EPI == EPI_RES) {
                    float2 rr2 = *(const float2*)&res[(size_t)rr * ldc + c];
                    *(float2*)&((float*)Co)[(size_t)rr * ldc + c] = make_float2(v0 + rr2.x, v1 + rr2.y);
                } else {
                    *(__half2*)&((__half*)Co)[(size_t)rr * ldc + c] = __floats2half2_rn(v0, v1);
                }
            }
        }
    }
}

// ---------------- fused flash attention (fp16, 128-row q tile, reg softmax) -------
#define FST 72   // flash smem row stride in halves (144 B, conflict-free)
#define KVB (64 * FST * 2)   // bytes per K or V stage

__global__ __launch_bounds__(256, 2)
void flash_attn_kernel(const __half* __restrict__ q, const __half* __restrict__ k,
                       const __half* __restrict__ vT, const uint8_t* __restrict__ rel8,
                       const float* __restrict__ table, __half* __restrict__ att) {
    extern __shared__ char smc[];
    __half* P = (__half*)smc;                           // 128 x FST (also Q staging)
    float* fst = (float*)(smc + 128 * FST * 2 + 4 * KVB);
    float* mrow = fst;          // 128
    float* lrow = fst + 128;
    float* pmax0 = fst + 256;
    float* pmax1 = fst + 384;
    float* psum0 = fst + 512;
    float* psum1 = fst + 640;
    float* tbl   = fst + 768;   // 9

    uint32_t sb  = (uint32_t)__cvta_generic_to_shared(smc);
    uint32_t P_u = sb;
    uint32_t K_u = sb + 128 * FST * 2;
    uint32_t V_u = K_u + 2 * KVB;

    int tid = threadIdx.x;
    int warp = tid >> 5, lane = tid & 31;
    int gid = lane >> 2, tig = lane & 3;
    int wm = warp & 3, wn = warp >> 2;                  // warp tile 32 rows x 32 cols
    int bh = blockIdx.y, b = bh >> 3, h = bh & 7;
    int m0 = blockIdx.x * 128;

    const __half* Q  = q  + (size_t)b * N_ * C_ + h * HD_;
    const __half* Kp = k  + (size_t)b * N_ * C_ + h * HD_;
    const __half* Vt = vT + (size_t)bh * HD_ * N_;
    const uint8_t* relb = rel8 + (size_t)b * N_ * N_;

    if (tid < 128) { mrow[tid] = -INFINITY; lrow[tid] = 0.0f; }
    if (tid < 9)   tbl[tid] = (tid == 0) ? 0.0f : table[(tid - 1) * H_ + h];

    auto load_kv = [&](int stage, int kn0) {
        uint32_t kb = K_u + stage * KVB;
        uint32_t vb = V_u + stage * KVB;
#pragma unroll
        for (int i = 0; i < 2; i++) {
            int f = tid + i * 256;
            int r = f >> 3, c = (f & 7) << 3;           // 64 rows x 8 chunks
            cp16(kb + (r * FST + c) * 2, Kp + (size_t)(kn0 + r) * C_ + c);
            cp16(vb + (r * FST + c) * 2, Vt + (size_t)r * N_ + kn0 + c);
        }
    };

    // stage Q (128x64 halves) into P region
#pragma unroll
    for (int i = 0; i < 4; i++) {
        int f = tid + i * 256;
        int r = f >> 3, c = (f & 7) << 3;
        cp16(P_u + (r * FST + c) * 2, Q + (size_t)(m0 + r) * C_ + c);
    }
    cp_commit();
    load_kv(0, 0);
    cp_commit();
    cp_wait<1>();
    __syncthreads();

    int li = lane >> 3;
    uint32_t a_off = ((((li & 1) * 8) + (lane & 7)) * FST + (li >> 1) * 8) * 2;
    uint32_t b_off = ((((li >> 1) * 8) + (lane & 7)) * FST + (li & 1) * 8) * 2;

    uint32_t qf[4][2][4];                               // 4 k16-steps, 2 mi
    {
        uint32_t qbase = P_u + (wm * 32) * FST * 2 + a_off;
#pragma unroll
        for (int ks = 0; ks < 4; ks++)
#pragma unroll
            for (int mi = 0; mi < 2; mi++)
                ldsm4(qf[ks][mi], qbase + mi * (16 * FST * 2) + ks * 32);
    }
    __syncthreads();                                    // P region free

    float acc_o[2][4][4] = {};

    for (int kt = 0; kt < N_ / 64; kt++) {
        int cur = kt & 1;
        int kn0 = kt * 64;
        if (kt + 1 < N_ / 64) {
            load_kv(cur ^ 1, (kt + 1) * 64);
            cp_commit();
            cp_wait<1>();
        } else {
            cp_wait<0>();
        }
        __syncthreads();

        // S = Q K^T (fp32 accum in regs)
        float acc_s[2][4][4] = {};
        {
            uint32_t kb = K_u + cur * KVB + (wn * 32) * FST * 2 + b_off;
#pragma unroll
            for (int ks = 0; ks < 4; ks++) {
                uint32_t bf[2][4];
#pragma unroll
                for (int p = 0; p < 2; p++)
                    ldsm4(bf[p], kb + p * (16 * FST * 2) + ks * 32);
#pragma unroll
                for (int mi = 0; mi < 2; mi++)
#pragma unroll
                    for (int ni = 0; ni < 4; ni++)
                        mma_f16(acc_s[mi][ni], qf[ks][mi], &bf[ni >> 1][(ni & 1) * 2]);
            }
        }

        // Phase A: scale + rel bias in regs, per-warp row max
        float rmax[2][2] = {{-INFINITY, -INFINITY}, {-INFINITY, -INFINITY}};
#pragma unroll
        for (int mi = 0; mi < 2; mi++)
#pragma unroll
            for (int ni = 0; ni < 4; ni++)
#pragma unroll
                for (int e2 = 0; e2 < 2; e2++) {
                    int rr = wm * 32 + mi * 16 + gid + e2 * 8;
                    int col = kn0 + wn * 32 + ni * 8 + tig * 2;
                    uchar2 rv = *(const uchar2*)&relb[(size_t)(m0 + rr) * N_ + col];
                    float v0 = acc_s[mi][ni][e2 * 2]     * 0.125f + tbl[rv.x];
                    float v1 = acc_s[mi][ni][e2 * 2 + 1] * 0.125f + tbl[rv.y];
                    acc_s[mi][ni][e2 * 2] = v0;
                    acc_s[mi][ni][e2 * 2 + 1] = v1;
                    rmax[mi][e2] = fmaxf(rmax[mi][e2], fmaxf(v0, v1));
                }
#pragma unroll
        for (int mi = 0; mi < 2; mi++)
#pragma unroll
            for (int e2 = 0; e2 < 2; e2++) {
                float m = rmax[mi][e2];
                m = fmaxf(m, __shfl_xor_sync(0xffffffffu, m, 1));
                m = fmaxf(m, __shfl_xor_sync(0xffffffffu, m, 2));
                rmax[mi][e2] = m;
                if (tig == 0) {
                    int rr = wm * 32 + mi * 16 + gid + e2 * 8;
                    (wn == 0 ? pmax0 : pmax1)[rr] = m;
                }
            }
        __syncthreads();

        // Phase B: nm, exp in regs, row sums, P -> smem (fp16)
        float om[2][2], nm[2][2], rsum[2][2];
#pragma unroll
        for (int mi = 0; mi < 2; mi++)
#pragma unroll
            for (int e2 = 0; e2 < 2; e2++) {
                int rr = wm * 32 + mi * 16 + gid + e2 * 8;
                om[mi][e2] = mrow[rr];
                nm[mi][e2] = fmaxf(om[mi][e2], fmaxf(pmax0[rr], pmax1[rr]));
                rsum[mi][e2] = 0.0f;
            }
#pragma unroll
        for (int mi = 0; mi < 2; mi++)
#pragma unroll
            for (int ni = 0; ni < 4; ni++)
#pragma unroll
                for (int e2 = 0; e2 < 2; e2++) {
                    float p0 = __expf(acc_s[mi][ni][e2 * 2]     - nm[mi][e2]);
                    float p1 = __expf(acc_s[mi][ni][e2 * 2 + 1] - nm[mi][e2]);
                    rsum[mi][e2] += p0 + p1;
                    int rr = wm * 32 + mi * 16 + gid + e2 * 8;
                    int col = wn * 32 + ni * 8 + tig * 2;
                    *(__half2*)&P[rr * FST + col] = __floats2half2_rn(p0, p1);
                }
#pragma unroll
        for (int mi = 0; mi < 2; mi++)
#pragma unroll
            for (int e2 = 0; e2 < 2; e2++) {
                float s = rsum[mi][e2];
                s += __shfl_xor_sync(0xffffffffu, s, 1);
                s += __shfl_xor_sync(0xffffffffu, s, 2);
                if (tig == 0) {
                    int rr = wm * 32 + mi * 16 + gid + e2 * 8;
                    (wn == 0 ? psum0 : psum1)[rr] = s;
                }
            }
        __syncthreads();

        // Phase C: rescale acc_o, update stats (one lane per row)
#pragma unroll
        for (int mi = 0; mi < 2; mi++)
#pragma unroll
            for (int e2 = 0; e2 < 2; e2++) {
                float fr = __expf(om[mi][e2] - nm[mi][e2]);
#pragma unroll
                for (int ni = 0; ni < 4; ni++) {
                    acc_o[mi][ni][e2 * 2]     *= fr;
                    acc_o[mi][ni][e2 * 2 + 1] *= fr;
                }
                if (wn == 0 && tig == 0) {
                    int rr = wm * 32 + mi * 16 + gid + e2 * 8;
                    lrow[rr] = lrow[rr] * fr + psum0[rr] + psum1[rr];
                    mrow[rr] = nm[mi][e2];
                }
            }

        // O += P V
        {
            uint32_t pb = P_u + (wm * 32) * FST * 2 + a_off;
            uint32_t vb = V_u + cur * KVB + (wn * 32) * FST * 2 + b_off;
#pragma unroll
            for (int ks = 0; ks < 4; ks++) {
                uint32_t af[2][4];
#pragma unroll
                for (int mi = 0; mi < 2; mi++)
                    ldsm4(af[mi], pb + mi * (16 * FST * 2) + ks * 32);
                uint32_t bf[2][4];
#pragma unroll
                for (int p = 0; p < 2; p++)
                    ldsm4(bf[p], vb + p * (16 * FST * 2) + ks * 32);
#pragma unroll
                for (int mi = 0; mi < 2; mi++)
#pragma unroll
                    for (int ni = 0; ni < 4; ni++)
                        mma_f16(acc_o[mi][ni], af[mi], &bf[ni >> 1][(ni & 1) * 2]);
            }
        }
        __syncthreads();
    }

    // finalize
#pragma unroll
    for (int mi = 0; mi < 2; mi++)
#pragma unroll
        for (int ni = 0; ni < 4; ni++) {
            int row = wm * 32 + mi * 16 + gid;
            int col = wn * 32 + ni * 8 + tig * 2;
#pragma unroll
            for (int e2 = 0; e2 < 2; e2++) {
                int rr = row + e2 * 8;
                float inv = 1.0f / lrow[rr];
                *(__half2*)&att[((size_t)b * N_ + m0 + rr) * C_ + h * HD_ + col] =
                    __floats2half2_rn(acc_o[mi][ni][e2 * 2] * inv, acc_o[mi][ni][e2 * 2 + 1] * inv);
            }
        }
}

// ---------------- launch -----------------------------------------------------------
extern "C" void kernel_launch(void* const* d_in, const int* in_sizes, int n_in,
                              void* d_out, int out_size) {
    const float* x     = (const float*)d_in[0];
    const int*   eidx  = (const int*)  d_in[1];
    const int*   etype = (const int*)  d_in[2];
    const float* q_w   = (const float*)d_in[3];
    const float* q_b   = (const float*)d_in[4];
    const float* k_w   = (const float*)d_in[5];
    const float* k_b   = (const float*)d_in[6];
    const float* v_w   = (const float*)d_in[7];
    const float* v_b   = (const float*)d_in[8];
    const float* o_w   = (const float*)d_in[9];
    const float* o_b   = (const float*)d_in[10];
    const float* table = (const float*)d_in[11];
    const float* ln1_g = (const float*)d_in[12];
    const float* ln1_b = (const float*)d_in[13];
    const float* ln2_g = (const float*)d_in[14];
    const float* ln2_b = (const float*)d_in[15];
    const float* f1_w  = (const float*)d_in[16];
    const float* f1_b  = (const float*)d_in[17];
    const float* f2_w  = (const float*)d_in[18];
    const float* f2_b  = (const float*)d_in[19];
    float* out = (float*)d_out;

    void *p_rel, *p_rel8, *p_h, *p_q, *p_k, *p_v, *p_vT, *p_att, *p_res, *p_h2, *p_mid;
    void *p_wq, *p_wk, *p_wv, *p_wo, *p_f1, *p_f2;
    cudaGetSymbolAddress(&p_rel,  g_rel);
    cudaGetSymbolAddress(&p_rel8, g_rel8);
    cudaGetSymbolAddress(&p_h,   g_h);
    cudaGetSymbolAddress(&p_q,   g_q);
    cudaGetSymbolAddress(&p_k,   g_k);
    cudaGetSymbolAddress(&p_v,   g_v);
    cudaGetSymbolAddress(&p_vT,  g_vT);
    cudaGetSymbolAddress(&p_att, g_att);
    cudaGetSymbolAddress(&p_res, g_res);
    cudaGetSymbolAddress(&p_h2,  g_h2);
    cudaGetSymbolAddress(&p_mid, g_mid);
    cudaGetSymbolAddress(&p_wq,  g_wqT);
    cudaGetSymbolAddress(&p_wk,  g_wkT);
    cudaGetSymbolAddress(&p_wv,  g_wvT);
    cudaGetSymbolAddress(&p_wo,  g_woT);
    cudaGetSymbolAddress(&p_f1,  g_f1T);
    cudaGetSymbolAddress(&p_f2,  g_f2T);

    const int SMEM_MM    = 2 * (128 * WST * 2 * 2);                       // 40960
    const int SMEM_FLASH = 128 * FST * 2 + 4 * KVB + (6 * 128 + 16) * 4;  // ~58.5 KB
    cudaFuncSetAttribute(mm_tc<EPI_BIAS>, cudaFuncAttributeMaxDynamicSharedMemorySize, SMEM_MM);
    cudaFuncSetAttribute(mm_tc<EPI_RES>,  cudaFuncAttributeMaxDynamicSharedMemorySize, SMEM_MM);
    cudaFuncSetAttribute(mm_tc<EPI_GELU>, cudaFuncAttributeMaxDynamicSharedMemorySize, SMEM_MM);
    cudaFuncSetAttribute(flash_attn_kernel, cudaFuncAttributeMaxDynamicSharedMemorySize, SMEM_FLASH);

    const int rows = B_ * N_;
    __half* fh  = (__half*)p_h;  __half* fq = (__half*)p_q;  __half* fk = (__half*)p_k;
    __half* fv  = (__half*)p_v;  __half* fvT = (__half*)p_vT;
    __half* fatt = (__half*)p_att; float* fres = (float*)p_res;
    __half* fh2 = (__half*)p_h2; __half* fmid = (__half*)p_mid;
    int* frel = (int*)p_rel;

    // 1) batched weight prep
    transpose_all_kernel<<<3072, 256>>>(q_w, k_w, v_w, o_w, f1_w, f2_w);
    // 2-4) relation map + pack
    init_rel_kernel<<<2048, 256>>>((int4*)p_rel);
    scatter_edges_kernel<<<(B_ * E_) / 256, 256>>>(eidx, etype, frel);
    pack_rel_kernel<<<1024, 256>>>((const int4*)p_rel, (uchar4*)p_rel8);
    // 5) LN1
    ln_kernel<<<rows, 256>>>(x, ln1_g, ln1_b, fh);
    // 6) fused QKV
    mm_tc<EPI_BIAS><<<dim3(C_ / 128, rows / 128, 3), 256, SMEM_MM>>>(
        fh, (__half*)p_wq, (__half*)p_wk, (__half*)p_wv, q_b, k_b, v_b, nullptr,
        fq, fk, fv, C_, C_, C_, C_);
    // 7) transpose V per head
    transpose_v_kernel<<<dim3(N_ / 32, HD_ / 32, B_ * H_), 256>>>(fv, fvT);
    // 8) fused attention
    flash_attn_kernel<<<dim3(N_ / 128, B_ * H_), 256, SMEM_FLASH>>>(
        fq, fk, fvT, (const uint8_t*)p_rel8, table, fatt);
    // 9) output projection + residual(x)
    mm_tc<EPI_RES><<<dim3(C_ / 128, rows / 128, 1), 256, SMEM_MM>>>(
        fatt, (__half*)p_wo, nullptr, nullptr, o_b, nullptr, nullptr, x,
        fres, nullptr, nullptr, C_, C_, C_, C_);
    // 10) LN2
    ln_kernel<<<rows, 256>>>(fres, ln2_g, ln2_b, fh2);
    // 11-12) FFN
    mm_tc<EPI_GELU><<<dim3(FF_ / 128, rows / 128, 1), 256, SMEM_MM>>>(
        fh2, (__half*)p_f1, nullptr, nullptr, f1_b, nullptr, nullptr, nullptr,
        fmid, nullptr, nullptr, C_, C_, C_, FF_);
    mm_tc<EPI_RES><<<dim3(C_ / 128, rows / 128, 1), 256, SMEM_MM>>>(
        fmid, (__half*)p_f2, nullptr, nullptr, f2_b, nullptr, nullptr, fres,
        out, nullptr, nullptr, FF_, FF_, FF_, C_);
}

// round 7
// speedup vs baseline: 7.2488x; 1.0181x over previous
#include <cuda_runtime.h>
#include <cuda_fp16.h>
#include <math.h>
#include <stdint.h>

#define B_  4
#define N_  1024
#define C_  512
#define H_  8
#define HD_ 64
#define E_  16384
#define FF_ 2048

// ---------------- scratch ----------------------------------------------------
__device__ uint8_t g_rel8[B_ * N_ * N_];              // max(r)+1, 0 = no edge
__device__ __half g_h  [B_ * N_ * C_];
__device__ __half g_q  [B_ * N_ * C_];
__device__ __half g_k  [B_ * N_ * C_];
__device__ __half g_v  [B_ * N_ * C_];
__device__ __half g_att[B_ * N_ * C_];
__device__ float  g_res[B_ * N_ * C_];
__device__ __half g_h2 [B_ * N_ * C_];
__device__ __half g_mid[B_ * N_ * FF_];
// transposed (n-major) fp16 weights
__device__ __half g_wqT[C_ * C_];
__device__ __half g_wkT[C_ * C_];
__device__ __half g_wvT[C_ * C_];
__device__ __half g_woT[C_ * C_];
__device__ __half g_f1T[FF_ * C_];
__device__ __half g_f2T[C_ * FF_];

// ---------------- helpers -----------------------------------------------------
__device__ __forceinline__ void mma_f16(float* c, const uint32_t* a, const uint32_t* b) {
    asm volatile(
        "mma.sync.aligned.m16n8k16.row.col.f32.f16.f16.f32 "
        "{%0,%1,%2,%3}, {%4,%5,%6,%7}, {%8,%9}, {%0,%1,%2,%3};\n"
        : "+f"(c[0]), "+f"(c[1]), "+f"(c[2]), "+f"(c[3])
        : "r"(a[0]), "r"(a[1]), "r"(a[2]), "r"(a[3]), "r"(b[0]), "r"(b[1]));
}

__device__ __forceinline__ void ldsm4(uint32_t* r, uint32_t addr) {
    asm volatile("ldmatrix.sync.aligned.m8n8.x4.shared.b16 {%0,%1,%2,%3}, [%4];\n"
                 : "=r"(r[0]), "=r"(r[1]), "=r"(r[2]), "=r"(r[3]) : "r"(addr));
}

__device__ __forceinline__ void ldsm4t(uint32_t* r, uint32_t addr) {
    asm volatile("ldmatrix.sync.aligned.m8n8.x4.trans.shared.b16 {%0,%1,%2,%3}, [%4];\n"
                 : "=r"(r[0]), "=r"(r[1]), "=r"(r[2]), "=r"(r[3]) : "r"(addr));
}

__device__ __forceinline__ void cp16(uint32_t dst, const void* src) {
    asm volatile("cp.async.cg.shared.global [%0], [%1], 16;\n" :: "r"(dst), "l"(src));
}
__device__ __forceinline__ void cp_commit() { asm volatile("cp.async.commit_group;\n"); }
template <int NMAX>
__device__ __forceinline__ void cp_wait() { asm volatile("cp.async.wait_group %0;\n" :: "n"(NMAX)); }

// ---------------- batched weight transpose + fp16 convert -----------------------
__global__ __launch_bounds__(256)
void transpose_all_kernel(const float* __restrict__ q_w, const float* __restrict__ k_w,
                          const float* __restrict__ v_w, const float* __restrict__ o_w,
                          const float* __restrict__ f1_w, const float* __restrict__ f2_w) {
    __shared__ float t[32][33];
    int blk = blockIdx.x;
    const float* src;
    __half* dst;
    int R, Ccols, ti;
    if (blk < 1024) {
        int m = blk >> 8; ti = blk & 255;
        src = (m == 0) ? q_w : (m == 1) ? k_w : (m == 2) ? v_w : o_w;
        dst = (m == 0) ? g_wqT : (m == 1) ? g_wkT : (m == 2) ? g_wvT : g_woT;
        R = C_; Ccols = C_;
    } else if (blk < 2048) {
        ti = blk - 1024; src = f1_w; dst = g_f1T; R = C_; Ccols = FF_;
    } else {
        ti = blk - 2048; src = f2_w; dst = g_f2T; R = FF_; Ccols = C_;
    }
    int ct = Ccols >> 5;
    int c0 = (ti % ct) * 32, r0 = (ti / ct) * 32;
    int tx = threadIdx.x & 31, ty = threadIdx.x >> 5;
#pragma unroll
    for (int i = 0; i < 4; i++)
        t[ty + i * 8][tx] = src[(size_t)(r0 + ty + i * 8) * Ccols + c0 + tx];
    __syncthreads();
#pragma unroll
    for (int i = 0; i < 4; i++)
        dst[(size_t)(c0 + ty + i * 8) * R + r0 + tx] = __float2half_rn(t[tx][ty + i * 8]);
}

// ---------------- rel8 map: zero + byte-max scatter ------------------------------
__global__ void init_rel8_kernel(uint4* __restrict__ rel16) {
    int idx = blockIdx.x * blockDim.x + threadIdx.x;
    int total = (B_ * N_ * N_) / 16;
    uint4 z = make_uint4(0, 0, 0, 0);
    for (int i = idx; i < total; i += gridDim.x * blockDim.x) rel16[i] = z;
}

__global__ void scatter_edges8_kernel(const int* __restrict__ edge_index,
                                      const int* __restrict__ edge_type,
                                      unsigned int* __restrict__ rel8w) {
    int idx = blockIdx.x * blockDim.x + threadIdx.x;
    if (idx >= B_ * E_) return;
    int b = idx / E_;
    int e = idx - b * E_;
    int s = edge_index[b * 2 * E_ + e];
    int t = edge_index[b * 2 * E_ + E_ + e];
    int r = edge_type[b * E_ + e];
    if (s < 0 || s >= N_ || t < 0 || t >= N_) return;
    unsigned int cell = (unsigned int)(b * N_ * N_ + s * N_ + t);
    unsigned int word = cell >> 2, sh = (cell & 3u) * 8u;
    unsigned int val = (unsigned int)(r + 1);
    unsigned int old = rel8w[word];
    while (((old >> sh) & 0xffu) < val) {
        unsigned int assumed = old;
        unsigned int newv = (old & ~(0xffu << sh)) | (val << sh);
        old = atomicCAS(&rel8w[word], assumed, newv);
        if (old == assumed) break;
    }
}

// ---------------- layernorm (fp32 in, fp16 out) ---------------------------------
__global__ __launch_bounds__(256)
void ln_kernel(const float* __restrict__ x, const float* __restrict__ gma,
               const float* __restrict__ bta, __half* __restrict__ y) {
    int row = blockIdx.x;
    const float* xr = x + (size_t)row * C_;
    int t = threadIdx.x;
    float2 xv = *(const float2*)&xr[t * 2];
    __shared__ float sbuf[256];
    sbuf[t] = xv.x + xv.y;
    __syncthreads();
    for (int o = 128; o > 0; o >>= 1) { if (t < o) sbuf[t] += sbuf[t + o]; __syncthreads(); }
    float mean = sbuf[0] * (1.0f / C_);
    __syncthreads();
    float d0 = xv.x - mean, d1 = xv.y - mean;
    sbuf[t] = d0 * d0 + d1 * d1;
    __syncthreads();
    for (int o = 128; o > 0; o >>= 1) { if (t < o) sbuf[t] += sbuf[t + o]; __syncthreads(); }
    float inv = rsqrtf(sbuf[0] * (1.0f / C_) + 1e-5f);
    float2 g = *(const float2*)&gma[t * 2];
    float2 bb = *(const float2*)&bta[t * 2];
    *(__half2*)&y[(size_t)row * C_ + t * 2] =
        __floats2half2_rn(d0 * inv * g.x + bb.x, d1 * inv * g.y + bb.y);
}

// ---------------- pipelined fp16 GEMM (3-stage) ------------------------------------
enum { EPI_BIAS = 0, EPI_GELU = 1, EPI_RES = 2 };
#define WST 40   // smem row stride in halves

template <int EPI>
__global__ __launch_bounds__(256, 2)
void mm_tc(const __half* __restrict__ Abase,
           const __half* __restrict__ W0, const __half* __restrict__ W1,
           const __half* __restrict__ W2,
           const float* __restrict__ bi0, const float* __restrict__ bi1,
           const float* __restrict__ bi2,
           const float* __restrict__ res,
           void* __restrict__ O0, void* __restrict__ O1, void* __restrict__ O2,
           int K, int lda, int ldb, int ldc) {
    constexpr int BM = 128, BN = 128, BK = 32;
    constexpr int MI = 4, NI = 4, WARPS_M = 2;
    constexpr int WM = MI * 16, WN = NI * 8;
    constexpr int AS_B = BM * WST * 2;
    constexpr int STG_B = AS_B + BN * WST * 2;

    extern __shared__ char smc[];
    uint32_t sbase = (uint32_t)__cvta_generic_to_shared(smc);

    int tid = threadIdx.x;
    int warp = tid >> 5, lane = tid & 31;
    int gid = lane >> 2, tig = lane & 3;
    int wm = warp % WARPS_M, wn = warp / WARPS_M;
    int m0 = blockIdx.y * BM, n0 = blockIdx.x * BN;

    int z = blockIdx.z;
    const __half* A   = Abase;
    const __half* Bm  = (z == 0) ? W0 : ((z == 1) ? W1 : W2);
    const float* bias = (z == 0) ? bi0 : ((z == 1) ? bi1 : bi2);
    void* Co          = (z == 0) ? O0 : ((z == 1) ? O1 : O2);

    int li = lane >> 3;
    uint32_t a_off = ((((li & 1) * 8) + (lane & 7)) * WST + (li >> 1) * 8) * 2;
    uint32_t b_off = ((((li >> 1) * 8) + (lane & 7)) * WST + (li & 1) * 8) * 2;

    float acc[MI][NI][4] = {};

    auto load_tile = [&](int stage, int k0) {
        uint32_t ab = sbase + stage * STG_B;
#pragma unroll
        for (int i = 0; i < 2; i++) {
            int f = tid + i * 256;
            int r = f >> 2, c = (f & 3) << 3;
            cp16(ab + (r * WST + c) * 2, A + (size_t)(m0 + r) * lda + k0 + c);
        }
        uint32_t bb = sbase + stage * STG_B + AS_B;
#pragma unroll
        for (int i = 0; i < 2; i++) {
            int f = tid + i * 256;
            int r = f >> 2, c = (f & 3) << 3;
            cp16(bb + (r * WST + c) * 2, Bm + (size_t)(n0 + r) * ldb + k0 + c);
        }
    };

    int KT = K / BK;
    load_tile(0, 0); cp_commit();
    load_tile(1, BK); cp_commit();

    for (int kt = 0; kt < KT; kt++) {
        int cur = kt % 3;
        if (kt + 2 < KT) { load_tile((kt + 2) % 3, (kt + 2) * BK); cp_commit(); }
        int rem = KT - 1 - kt;
        if (rem >= 2)      cp_wait<2>();
        else if (rem == 1) cp_wait<1>();
        else               cp_wait<0>();
        __syncthreads();

        uint32_t a_s = sbase + cur * STG_B + (wm * WM) * WST * 2 + a_off;
        uint32_t b_s = sbase + cur * STG_B + AS_B + (wn * WN) * WST * 2 + b_off;
#pragma unroll
        for (int ks = 0; ks < 2; ks++) {
            uint32_t af[MI][4];
#pragma unroll
            for (int mi = 0; mi < MI; mi++)
                ldsm4(af[mi], a_s + mi * (16 * WST * 2) + ks * 32);
            uint32_t bf[NI / 2][4];
#pragma unroll
            for (int p = 0; p < NI / 2; p++)
                ldsm4(bf[p], b_s + p * (16 * WST * 2) + ks * 32);
#pragma unroll
            for (int mi = 0; mi < MI; mi++)
#pragma unroll
                for (int ni = 0; ni < NI; ni++)
                    mma_f16(acc[mi][ni], af[mi], &bf[ni >> 1][(ni & 1) * 2]);
        }
        __syncthreads();
    }

#pragma unroll
    for (int mi = 0; mi < MI; mi++) {
#pragma unroll
        for (int ni = 0; ni < NI; ni++) {
            int r = m0 + wm * WM + mi * 16 + gid;
            int c = n0 + wn * WN + ni * 8 + tig * 2;
#pragma unroll
            for (int e2 = 0; e2 < 2; e2++) {
                int rr = r + e2 * 8;
                float v0 = acc[mi][ni][e2 * 2];
                float v1 = acc[mi][ni][e2 * 2 + 1];
                float2 bb = *(const float2*)&bias[c];
                v0 += bb.x; v1 += bb.y;
                if (EPI == EPI_GELU) {
                    v0 = 0.5f * v0 * (1.0f + erff(v0 * 0.70710678118654752f));
                    v1 = 0.5f * v1 * (1.0f + erff(v1 * 0.70710678118654752f));
                }
                if (EPI == EPI_RES) {
                    float2 rr2 = *(const float2*)&res[(size_t)rr * ldc + c];
                    *(float2*)&((float*)Co)[(size_t)rr * ldc + c] = make_float2(v0 + rr2.x, v1 + rr2.y);
                } else {
                    *(__half2*)&((__half*)Co)[(size_t)rr * ldc + c] = __floats2half2_rn(v0, v1);
                }
            }
        }
    }
}

// ---------------- fused flash attention (fp16; V via ldmatrix.trans) ---------------
#define FST 72
#define KVB (64 * FST * 2)

__global__ __launch_bounds__(256, 2)
void flash_attn_kernel(const __half* __restrict__ q, const __half* __restrict__ k,
                       const __half* __restrict__ v, const uint8_t* __restrict__ rel8,
                       const float* __restrict__ table, __half* __restrict__ att) {
    extern __shared__ char smc[];
    __half* P = (__half*)smc;
    float* fst = (float*)(smc + 128 * FST * 2 + 4 * KVB);
    float* mrow = fst;
    float* lrow = fst + 128;
    float* pmax0 = fst + 256;
    float* pmax1 = fst + 384;
    float* psum0 = fst + 512;
    float* psum1 = fst + 640;
    float* tbl   = fst + 768;

    uint32_t sb  = (uint32_t)__cvta_generic_to_shared(smc);
    uint32_t P_u = sb;
    uint32_t K_u = sb + 128 * FST * 2;
    uint32_t V_u = K_u + 2 * KVB;

    int tid = threadIdx.x;
    int warp = tid >> 5, lane = tid & 31;
    int gid = lane >> 2, tig = lane & 3;
    int wm = warp & 3, wn = warp >> 2;
    int bh = blockIdx.y, b = bh >> 3, h = bh & 7;
    int m0 = blockIdx.x * 128;

    const __half* Q  = q + (size_t)b * N_ * C_ + h * HD_;
    const __half* Kp = k + (size_t)b * N_ * C_ + h * HD_;
    const __half* Vp = v + (size_t)b * N_ * C_ + h * HD_;
    const uint8_t* relb = rel8 + (size_t)b * N_ * N_;

    if (tid < 128) { mrow[tid] = -INFINITY; lrow[tid] = 0.0f; }
    if (tid < 9)   tbl[tid] = (tid == 0) ? 0.0f : table[(tid - 1) * H_ + h];

    auto load_kv = [&](int stage, int kn0) {
        uint32_t kb = K_u + stage * KVB;
        uint32_t vb = V_u + stage * KVB;
#pragma unroll
        for (int i = 0; i < 2; i++) {
            int f = tid + i * 256;
            int r = f >> 3, c = (f & 7) << 3;
            cp16(kb + (r * FST + c) * 2, Kp + (size_t)(kn0 + r) * C_ + c);
            cp16(vb + (r * FST + c) * 2, Vp + (size_t)(kn0 + r) * C_ + c);  // [seq][d]
        }
    };

    // stage Q (128x64) into P region
#pragma unroll
    for (int i = 0; i < 4; i++) {
        int f = tid + i * 256;
        int r = f >> 3, c = (f & 7) << 3;
        cp16(P_u + (r * FST + c) * 2, Q + (size_t)(m0 + r) * C_ + c);
    }
    cp_commit();
    load_kv(0, 0);
    cp_commit();
    cp_wait<1>();
    __syncthreads();

    int li = lane >> 3;
    uint32_t a_off = ((((li & 1) * 8) + (lane & 7)) * FST + (li >> 1) * 8) * 2;
    uint32_t b_off = ((((li >> 1) * 8) + (lane & 7)) * FST + (li & 1) * 8) * 2;

    uint32_t qf[4][2][4];
    {
        uint32_t qbase = P_u + (wm * 32) * FST * 2 + a_off;
#pragma unroll
        for (int ks = 0; ks < 4; ks++)
#pragma unroll
            for (int mi = 0; mi < 2; mi++)
                ldsm4(qf[ks][mi], qbase + mi * (16 * FST * 2) + ks * 32);
    }
    __syncthreads();

    float acc_o[2][4][4] = {};

    for (int kt = 0; kt < N_ / 64; kt++) {
        int cur = kt & 1;
        int kn0 = kt * 64;
        if (kt + 1 < N_ / 64) {
            load_kv(cur ^ 1, (kt + 1) * 64);
            cp_commit();
            cp_wait<1>();
        } else {
            cp_wait<0>();
        }
        __syncthreads();

        // S = Q K^T
        float acc_s[2][4][4] = {};
        {
            uint32_t kb = K_u + cur * KVB + (wn * 32) * FST * 2 + b_off;
#pragma unroll
            for (int ks = 0; ks < 4; ks++) {
                uint32_t bf[2][4];
#pragma unroll
                for (int p = 0; p < 2; p++)
                    ldsm4(bf[p], kb + p * (16 * FST * 2) + ks * 32);
#pragma unroll
                for (int mi = 0; mi < 2; mi++)
#pragma unroll
                    for (int ni = 0; ni < 4; ni++)
                        mma_f16(acc_s[mi][ni], qf[ks][mi], &bf[ni >> 1][(ni & 1) * 2]);
            }
        }

        // Phase A: scale + rel bias, per-warp row max
        float rmax[2][2] = {{-INFINITY, -INFINITY}, {-INFINITY, -INFINITY}};
#pragma unroll
        for (int mi = 0; mi < 2; mi++)
#pragma unroll
            for (int ni = 0; ni < 4; ni++)
#pragma unroll
                for (int e2 = 0; e2 < 2; e2++) {
                    int rr = wm * 32 + mi * 16 + gid + e2 * 8;
                    int col = kn0 + wn * 32 + ni * 8 + tig * 2;
                    uchar2 rv = *(const uchar2*)&relb[(size_t)(m0 + rr) * N_ + col];
                    float v0 = acc_s[mi][ni][e2 * 2]     * 0.125f + tbl[rv.x];
                    float v1 = acc_s[mi][ni][e2 * 2 + 1] * 0.125f + tbl[rv.y];
                    acc_s[mi][ni][e2 * 2] = v0;
                    acc_s[mi][ni][e2 * 2 + 1] = v1;
                    rmax[mi][e2] = fmaxf(rmax[mi][e2], fmaxf(v0, v1));
                }
#pragma unroll
        for (int mi = 0; mi < 2; mi++)
#pragma unroll
            for (int e2 = 0; e2 < 2; e2++) {
                float m = rmax[mi][e2];
                m = fmaxf(m, __shfl_xor_sync(0xffffffffu, m, 1));
                m = fmaxf(m, __shfl_xor_sync(0xffffffffu, m, 2));
                if (tig == 0) {
                    int rr = wm * 32 + mi * 16 + gid + e2 * 8;
                    (wn == 0 ? pmax0 : pmax1)[rr] = m;
                }
            }
        __syncthreads();

        // Phase B: exp in regs, row sums, P -> smem fp16
        float om[2][2], nm[2][2], rsum[2][2];
#pragma unroll
        for (int mi = 0; mi < 2; mi++)
#pragma unroll
            for (int e2 = 0; e2 < 2; e2++) {
                int rr = wm * 32 + mi * 16 + gid + e2 * 8;
                om[mi][e2] = mrow[rr];
                nm[mi][e2] = fmaxf(om[mi][e2], fmaxf(pmax0[rr], pmax1[rr]));
                rsum[mi][e2] = 0.0f;
            }
#pragma unroll
        for (int mi = 0; mi < 2; mi++)
#pragma unroll
            for (int ni = 0; ni < 4; ni++)
#pragma unroll
                for (int e2 = 0; e2 < 2; e2++) {
                    float p0 = __expf(acc_s[mi][ni][e2 * 2]     - nm[mi][e2]);
                    float p1 = __expf(acc_s[mi][ni][e2 * 2 + 1] - nm[mi][e2]);
                    rsum[mi][e2] += p0 + p1;
                    int rr = wm * 32 + mi * 16 + gid + e2 * 8;
                    int col = wn * 32 + ni * 8 + tig * 2;
                    *(__half2*)&P[rr * FST + col] = __floats2half2_rn(p0, p1);
                }
#pragma unroll
        for (int mi = 0; mi < 2; mi++)
#pragma unroll
            for (int e2 = 0; e2 < 2; e2++) {
                float s = rsum[mi][e2];
                s += __shfl_xor_sync(0xffffffffu, s, 1);
                s += __shfl_xor_sync(0xffffffffu, s, 2);
                if (tig == 0) {
                    int rr = wm * 32 + mi * 16 + gid + e2 * 8;
                    (wn == 0 ? psum0 : psum1)[rr] = s;
                }
            }
        __syncthreads();

        // Phase C: rescale acc_o, update stats
#pragma unroll
        for (int mi = 0; mi < 2; mi++)
#pragma unroll
            for (int e2 = 0; e2 < 2; e2++) {
                float fr = __expf(om[mi][e2] - nm[mi][e2]);
#pragma unroll
                for (int ni = 0; ni < 4; ni++) {
                    acc_o[mi][ni][e2 * 2]     *= fr;
                    acc_o[mi][ni][e2 * 2 + 1] *= fr;
                }
                if (wn == 0 && tig == 0) {
                    int rr = wm * 32 + mi * 16 + gid + e2 * 8;
                    lrow[rr] = lrow[rr] * fr + psum0[rr] + psum1[rr];
                    mrow[rr] = nm[mi][e2];
                }
            }

        // O += P V  (B fragments from natural [seq][d] tile via ldmatrix.trans)
        {
            uint32_t pb = P_u + (wm * 32) * FST * 2 + a_off;
            uint32_t vb = V_u + cur * KVB + (wn * 32) * 2 + a_off;  // trans: same lane map as A
#pragma unroll
            for (int ks = 0; ks < 4; ks++) {
                uint32_t af[2][4];
#pragma unroll
                for (int mi = 0; mi < 2; mi++)
                    ldsm4(af[mi], pb + mi * (16 * FST * 2) + ks * 32);
                uint32_t bf[2][4];
#pragma unroll
                for (int p = 0; p < 2; p++)
                    ldsm4t(bf[p], vb + ks * (16 * FST * 2) + p * 32);
#pragma unroll
                for (int mi = 0; mi < 2; mi++)
#pragma unroll
                    for (int ni = 0; ni < 4; ni++)
                        mma_f16(acc_o[mi][ni], af[mi], &bf[ni >> 1][(ni & 1) * 2]);
            }
        }
        __syncthreads();
    }

    // finalize
#pragma unroll
    for (int mi = 0; mi < 2; mi++)
#pragma unroll
        for (int ni = 0; ni < 4; ni++) {
            int row = wm * 32 + mi * 16 + gid;
            int col = wn * 32 + ni * 8 + tig * 2;
#pragma unroll
            for (int e2 = 0; e2 < 2; e2++) {
                int rr = row + e2 * 8;
                float inv = 1.0f / lrow[rr];
                *(__half2*)&att[((size_t)b * N_ + m0 + rr) * C_ + h * HD_ + col] =
                    __floats2half2_rn(acc_o[mi][ni][e2 * 2] * inv, acc_o[mi][ni][e2 * 2 + 1] * inv);
            }
        }
}

// ---------------- launch -----------------------------------------------------------
extern "C" void kernel_launch(void* const* d_in, const int* in_sizes, int n_in,
                              void* d_out, int out_size) {
    const float* x     = (const float*)d_in[0];
    const int*   eidx  = (const int*)  d_in[1];
    const int*   etype = (const int*)  d_in[2];
    const float* q_w   = (const float*)d_in[3];
    const float* q_b   = (const float*)d_in[4];
    const float* k_w   = (const float*)d_in[5];
    const float* k_b   = (const float*)d_in[6];
    const float* v_w   = (const float*)d_in[7];
    const float* v_b   = (const float*)d_in[8];
    const float* o_w   = (const float*)d_in[9];
    const float* o_b   = (const float*)d_in[10];
    const float* table = (const float*)d_in[11];
    const float* ln1_g = (const float*)d_in[12];
    const float* ln1_b = (const float*)d_in[13];
    const float* ln2_g = (const float*)d_in[14];
    const float* ln2_b = (const float*)d_in[15];
    const float* f1_w  = (const float*)d_in[16];
    const float* f1_b  = (const float*)d_in[17];
    const float* f2_w  = (const float*)d_in[18];
    const float* f2_b  = (const float*)d_in[19];
    float* out = (float*)d_out;

    void *p_rel8, *p_h, *p_q, *p_k, *p_v, *p_att, *p_res, *p_h2, *p_mid;
    void *p_wq, *p_wk, *p_wv, *p_wo, *p_f1, *p_f2;
    cudaGetSymbolAddress(&p_rel8, g_rel8);
    cudaGetSymbolAddress(&p_h,   g_h);
    cudaGetSymbolAddress(&p_q,   g_q);
    cudaGetSymbolAddress(&p_k,   g_k);
    cudaGetSymbolAddress(&p_v,   g_v);
    cudaGetSymbolAddress(&p_att, g_att);
    cudaGetSymbolAddress(&p_res, g_res);
    cudaGetSymbolAddress(&p_h2,  g_h2);
    cudaGetSymbolAddress(&p_mid, g_mid);
    cudaGetSymbolAddress(&p_wq,  g_wqT);
    cudaGetSymbolAddress(&p_wk,  g_wkT);
    cudaGetSymbolAddress(&p_wv,  g_wvT);
    cudaGetSymbolAddress(&p_wo,  g_woT);
    cudaGetSymbolAddress(&p_f1,  g_f1T);
    cudaGetSymbolAddress(&p_f2,  g_f2T);

    const int SMEM_MM    = 3 * (128 * WST * 2 * 2);                       // 61440
    const int SMEM_FLASH = 128 * FST * 2 + 4 * KVB + (6 * 128 + 16) * 4;
    cudaFuncSetAttribute(mm_tc<EPI_BIAS>, cudaFuncAttributeMaxDynamicSharedMemorySize, SMEM_MM);
    cudaFuncSetAttribute(mm_tc<EPI_RES>,  cudaFuncAttributeMaxDynamicSharedMemorySize, SMEM_MM);
    cudaFuncSetAttribute(mm_tc<EPI_GELU>, cudaFuncAttributeMaxDynamicSharedMemorySize, SMEM_MM);
    cudaFuncSetAttribute(flash_attn_kernel, cudaFuncAttributeMaxDynamicSharedMemorySize, SMEM_FLASH);

    const int rows = B_ * N_;
    __half* fh  = (__half*)p_h;  __half* fq = (__half*)p_q;  __half* fk = (__half*)p_k;
    __half* fv  = (__half*)p_v;
    __half* fatt = (__half*)p_att; float* fres = (float*)p_res;
    __half* fh2 = (__half*)p_h2; __half* fmid = (__half*)p_mid;

    // 1) weight prep
    transpose_all_kernel<<<3072, 256>>>(q_w, k_w, v_w, o_w, f1_w, f2_w);
    // 2) LN1
    ln_kernel<<<rows, 256>>>(x, ln1_g, ln1_b, fh);
    // 3) zero rel8
    init_rel8_kernel<<<1024, 256>>>((uint4*)p_rel8);
    // 4) fused QKV  (profile slot)
    mm_tc<EPI_BIAS><<<dim3(C_ / 128, rows / 128, 3), 256, SMEM_MM>>>(
        fh, (__half*)p_wq, (__half*)p_wk, (__half*)p_wv, q_b, k_b, v_b, nullptr,
        fq, fk, fv, C_, C_, C_, C_);
    // 5) scatter edges (byte max)
    scatter_edges8_kernel<<<(B_ * E_) / 256, 256>>>(eidx, etype, (unsigned int*)p_rel8);
    // 6) fused attention
    flash_attn_kernel<<<dim3(N_ / 128, B_ * H_), 256, SMEM_FLASH>>>(
        fq, fk, fv, (const uint8_t*)p_rel8, table, fatt);
    // 7) output projection + residual(x)
    mm_tc<EPI_RES><<<dim3(C_ / 128, rows / 128, 1), 256, SMEM_MM>>>(
        fatt, (__half*)p_wo, nullptr, nullptr, o_b, nullptr, nullptr, x,
        fres, nullptr, nullptr, C_, C_, C_, C_);
    // 8) LN2
    ln_kernel<<<rows, 256>>>(fres, ln2_g, ln2_b, fh2);
    // 9-10) FFN
    mm_tc<EPI_GELU><<<dim3(FF_ / 128, rows / 128, 1), 256, SMEM_MM>>>(
        fh2, (__half*)p_f1, nullptr, nullptr, f1_b, nullptr, nullptr, nullptr,
        fmid, nullptr, nullptr, C_, C_, C_, FF_);
    mm_tc<EPI_RES><<<dim3(C_ / 128, rows / 128, 1), 256, SMEM_MM>>>(
        fmid, (__half*)p_f2, nullptr, nullptr, f2_b, nullptr, nullptr, fres,
        out, nullptr, nullptr, FF_, FF_, FF_, C_);
}

// round 8
// speedup vs baseline: 8.1462x; 1.1238x over previous
#include <cuda_runtime.h>
#include <cuda_fp16.h>
#include <math.h>
#include <stdint.h>

#define B_  4
#define N_  1024
#define C_  512
#define H_  8
#define HD_ 64
#define E_  16384
#define FF_ 2048

// ---------------- scratch ----------------------------------------------------
__device__ uint8_t g_rel8[B_ * N_ * N_];              // max(r)+1, 0 = no edge
__device__ __half g_h  [B_ * N_ * C_];
__device__ __half g_q  [B_ * N_ * C_];
__device__ __half g_k  [B_ * N_ * C_];
__device__ __half g_v  [B_ * N_ * C_];
__device__ __half g_att[B_ * N_ * C_];
__device__ float  g_res[B_ * N_ * C_];
__device__ __half g_h2 [B_ * N_ * C_];
__device__ __half g_mid[B_ * N_ * FF_];
// transposed (n-major) fp16 weights
__device__ __half g_wqT[C_ * C_];
__device__ __half g_wkT[C_ * C_];
__device__ __half g_wvT[C_ * C_];
__device__ __half g_woT[C_ * C_];
__device__ __half g_f1T[FF_ * C_];
__device__ __half g_f2T[C_ * FF_];

// ---------------- helpers -----------------------------------------------------
__device__ __forceinline__ void mma_f16(float* c, const uint32_t* a, const uint32_t* b) {
    asm volatile(
        "mma.sync.aligned.m16n8k16.row.col.f32.f16.f16.f32 "
        "{%0,%1,%2,%3}, {%4,%5,%6,%7}, {%8,%9}, {%0,%1,%2,%3};\n"
        : "+f"(c[0]), "+f"(c[1]), "+f"(c[2]), "+f"(c[3])
        : "r"(a[0]), "r"(a[1]), "r"(a[2]), "r"(a[3]), "r"(b[0]), "r"(b[1]));
}

__device__ __forceinline__ void ldsm4(uint32_t* r, uint32_t addr) {
    asm volatile("ldmatrix.sync.aligned.m8n8.x4.shared.b16 {%0,%1,%2,%3}, [%4];\n"
                 : "=r"(r[0]), "=r"(r[1]), "=r"(r[2]), "=r"(r[3]) : "r"(addr));
}

__device__ __forceinline__ void ldsm4t(uint32_t* r, uint32_t addr) {
    asm volatile("ldmatrix.sync.aligned.m8n8.x4.trans.shared.b16 {%0,%1,%2,%3}, [%4];\n"
                 : "=r"(r[0]), "=r"(r[1]), "=r"(r[2]), "=r"(r[3]) : "r"(addr));
}

__device__ __forceinline__ void cp16(uint32_t dst, const void* src) {
    asm volatile("cp.async.cg.shared.global [%0], [%1], 16;\n" :: "r"(dst), "l"(src));
}
__device__ __forceinline__ void cp_commit() { asm volatile("cp.async.commit_group;\n"); }
template <int NMAX>
__device__ __forceinline__ void cp_wait() { asm volatile("cp.async.wait_group %0;\n" :: "n"(NMAX)); }

// ---------------- batched weight transpose + fp16 convert -----------------------
__global__ __launch_bounds__(256)
void transpose_all_kernel(const float* __restrict__ q_w, const float* __restrict__ k_w,
                          const float* __restrict__ v_w, const float* __restrict__ o_w,
                          const float* __restrict__ f1_w, const float* __restrict__ f2_w) {
    __shared__ float t[32][33];
    int blk = blockIdx.x;
    const float* src;
    __half* dst;
    int R, Ccols, ti;
    if (blk < 1024) {
        int m = blk >> 8; ti = blk & 255;
        src = (m == 0) ? q_w : (m == 1) ? k_w : (m == 2) ? v_w : o_w;
        dst = (m == 0) ? g_wqT : (m == 1) ? g_wkT : (m == 2) ? g_wvT : g_woT;
        R = C_; Ccols = C_;
    } else if (blk < 2048) {
        ti = blk - 1024; src = f1_w; dst = g_f1T; R = C_; Ccols = FF_;
    } else {
        ti = blk - 2048; src = f2_w; dst = g_f2T; R = FF_; Ccols = C_;
    }
    int ct = Ccols >> 5;
    int c0 = (ti % ct) * 32, r0 = (ti / ct) * 32;
    int tx = threadIdx.x & 31, ty = threadIdx.x >> 5;
#pragma unroll
    for (int i = 0; i < 4; i++)
        t[ty + i * 8][tx] = src[(size_t)(r0 + ty + i * 8) * Ccols + c0 + tx];
    __syncthreads();
#pragma unroll
    for (int i = 0; i < 4; i++)
        dst[(size_t)(c0 + ty + i * 8) * R + r0 + tx] = __float2half_rn(t[tx][ty + i * 8]);
}

// ---------------- rel8 map ---------------------------------------------------------
__global__ void init_rel8_kernel(uint4* __restrict__ rel16) {
    int idx = blockIdx.x * blockDim.x + threadIdx.x;
    int total = (B_ * N_ * N_) / 16;
    uint4 z = make_uint4(0, 0, 0, 0);
    for (int i = idx; i < total; i += gridDim.x * blockDim.x) rel16[i] = z;
}

__global__ void scatter_edges8_kernel(const int* __restrict__ edge_index,
                                      const int* __restrict__ edge_type,
                                      unsigned int* __restrict__ rel8w) {
    int idx = blockIdx.x * blockDim.x + threadIdx.x;
    if (idx >= B_ * E_) return;
    int b = idx / E_;
    int e = idx - b * E_;
    int s = edge_index[b * 2 * E_ + e];
    int t = edge_index[b * 2 * E_ + E_ + e];
    int r = edge_type[b * E_ + e];
    if (s < 0 || s >= N_ || t < 0 || t >= N_) return;
    unsigned int cell = (unsigned int)(b * N_ * N_ + s * N_ + t);
    unsigned int word = cell >> 2, sh = (cell & 3u) * 8u;
    unsigned int val = (unsigned int)(r + 1);
    unsigned int old = rel8w[word];
    while (((old >> sh) & 0xffu) < val) {
        unsigned int assumed = old;
        unsigned int newv = (old & ~(0xffu << sh)) | (val << sh);
        old = atomicCAS(&rel8w[word], assumed, newv);
        if (old == assumed) break;
    }
}

// ---------------- layernorm (fp32 in, fp16 out) ---------------------------------
__global__ __launch_bounds__(256)
void ln_kernel(const float* __restrict__ x, const float* __restrict__ gma,
               const float* __restrict__ bta, __half* __restrict__ y) {
    int row = blockIdx.x;
    const float* xr = x + (size_t)row * C_;
    int t = threadIdx.x;
    float2 xv = *(const float2*)&xr[t * 2];
    __shared__ float sbuf[256];
    sbuf[t] = xv.x + xv.y;
    __syncthreads();
    for (int o = 128; o > 0; o >>= 1) { if (t < o) sbuf[t] += sbuf[t + o]; __syncthreads(); }
    float mean = sbuf[0] * (1.0f / C_);
    __syncthreads();
    float d0 = xv.x - mean, d1 = xv.y - mean;
    sbuf[t] = d0 * d0 + d1 * d1;
    __syncthreads();
    for (int o = 128; o > 0; o >>= 1) { if (t < o) sbuf[t] += sbuf[t + o]; __syncthreads(); }
    float inv = rsqrtf(sbuf[0] * (1.0f / C_) + 1e-5f);
    float2 g = *(const float2*)&gma[t * 2];
    float2 bb = *(const float2*)&bta[t * 2];
    *(__half2*)&y[(size_t)row * C_ + t * 2] =
        __floats2half2_rn(d0 * inv * g.x + bb.x, d1 * inv * g.y + bb.y);
}

// ---------------- pipelined fp16 GEMM (BK=64, 2-stage) -----------------------------
enum { EPI_BIAS = 0, EPI_GELU = 1, EPI_RES = 2 };
#define WST 72   // smem row stride in halves (144 B)

template <int EPI>
__global__ __launch_bounds__(256, 2)
void mm_tc(const __half* __restrict__ Abase,
           const __half* __restrict__ W0, const __half* __restrict__ W1,
           const __half* __restrict__ W2,
           const float* __restrict__ bi0, const float* __restrict__ bi1,
           const float* __restrict__ bi2,
           const float* __restrict__ res,
           void* __restrict__ O0, void* __restrict__ O1, void* __restrict__ O2,
           int K, int lda, int ldb, int ldc) {
    constexpr int BM = 128, BN = 128, BK = 64;
    constexpr int MI = 4, NI = 4, WARPS_M = 2;
    constexpr int WM = MI * 16, WN = NI * 8;
    constexpr int AS_B = BM * WST * 2;           // 18432 B
    constexpr int STG_B = AS_B + BN * WST * 2;   // 36864 B

    extern __shared__ char smc[];
    uint32_t sbase = (uint32_t)__cvta_generic_to_shared(smc);

    int tid = threadIdx.x;
    int warp = tid >> 5, lane = tid & 31;
    int gid = lane >> 2, tig = lane & 3;
    int wm = warp % WARPS_M, wn = warp / WARPS_M;
    int m0 = blockIdx.y * BM, n0 = blockIdx.x * BN;

    int z = blockIdx.z;
    const __half* A   = Abase;
    const __half* Bm  = (z == 0) ? W0 : ((z == 1) ? W1 : W2);
    const float* bias = (z == 0) ? bi0 : ((z == 1) ? bi1 : bi2);
    void* Co          = (z == 0) ? O0 : ((z == 1) ? O1 : O2);

    int li = lane >> 3;
    uint32_t a_off = ((((li & 1) * 8) + (lane & 7)) * WST + (li >> 1) * 8) * 2;
    uint32_t b_off = ((((li >> 1) * 8) + (lane & 7)) * WST + (li & 1) * 8) * 2;

    float acc[MI][NI][4] = {};

    auto load_tile = [&](int stage, int k0) {
        uint32_t ab = sbase + stage * STG_B;
#pragma unroll
        for (int i = 0; i < 4; i++) {
            int f = tid + i * 256;
            int r = f >> 3, c = (f & 7) << 3;          // 128 rows x 8 chunks of 8 halves
            cp16(ab + (r * WST + c) * 2, A + (size_t)(m0 + r) * lda + k0 + c);
        }
        uint32_t bb = sbase + stage * STG_B + AS_B;
#pragma unroll
        for (int i = 0; i < 4; i++) {
            int f = tid + i * 256;
            int r = f >> 3, c = (f & 7) << 3;
            cp16(bb + (r * WST + c) * 2, Bm + (size_t)(n0 + r) * ldb + k0 + c);
        }
    };

    int KT = K / BK;
    load_tile(0, 0); cp_commit();

    for (int kt = 0; kt < KT; kt++) {
        int cur = kt & 1;
        if (kt + 1 < KT) {
            load_tile(cur ^ 1, (kt + 1) * BK);
            cp_commit();
            cp_wait<1>();
        } else {
            cp_wait<0>();
        }
        __syncthreads();

        uint32_t a_s = sbase + cur * STG_B + (wm * WM) * WST * 2 + a_off;
        uint32_t b_s = sbase + cur * STG_B + AS_B + (wn * WN) * WST * 2 + b_off;
#pragma unroll
        for (int ks = 0; ks < 4; ks++) {               // 4 x k16 per BK=64
            uint32_t af[MI][4];
#pragma unroll
            for (int mi = 0; mi < MI; mi++)
                ldsm4(af[mi], a_s + mi * (16 * WST * 2) + ks * 32);
            uint32_t bf[NI / 2][4];
#pragma unroll
            for (int p = 0; p < NI / 2; p++)
                ldsm4(bf[p], b_s + p * (16 * WST * 2) + ks * 32);
#pragma unroll
            for (int mi = 0; mi < MI; mi++)
#pragma unroll
                for (int ni = 0; ni < NI; ni++)
                    mma_f16(acc[mi][ni], af[mi], &bf[ni >> 1][(ni & 1) * 2]);
        }
        __syncthreads();
    }

#pragma unroll
    for (int mi = 0; mi < MI; mi++) {
#pragma unroll
        for (int ni = 0; ni < NI; ni++) {
            int r = m0 + wm * WM + mi * 16 + gid;
            int c = n0 + wn * WN + ni * 8 + tig * 2;
#pragma unroll
            for (int e2 = 0; e2 < 2; e2++) {
                int rr = r + e2 * 8;
                float v0 = acc[mi][ni][e2 * 2];
                float v1 = acc[mi][ni][e2 * 2 + 1];
                float2 bb = *(const float2*)&bias[c];
                v0 += bb.x; v1 += bb.y;
                if (EPI == EPI_GELU) {
                    v0 = 0.5f * v0 * (1.0f + erff(v0 * 0.70710678118654752f));
                    v1 = 0.5f * v1 * (1.0f + erff(v1 * 0.70710678118654752f));
                }
                if (EPI == EPI_RES) {
                    float2 rr2 = *(const float2*)&res[(size_t)rr * ldc + c];
                    *(float2*)&((float*)Co)[(size_t)rr * ldc + c] = make_float2(v0 + rr2.x, v1 + rr2.y);
                } else {
                    *(__half2*)&((__half*)Co)[(size_t)rr * ldc + c] = __floats2half2_rn(v0, v1);
                }
            }
        }
    }
}

// ---------------- fused flash attention: warp tile 16x64, reg-resident stats -------
#define FST 72
#define KVB (64 * FST * 2)

__global__ __launch_bounds__(256, 2)
void flash_attn_kernel(const __half* __restrict__ q, const __half* __restrict__ k,
                       const __half* __restrict__ v, const uint8_t* __restrict__ rel8,
                       const float* __restrict__ table, __half* __restrict__ att) {
    extern __shared__ char smc[];
    __half* P = (__half*)smc;                           // 128 x FST (also Q staging)
    float* tbl = (float*)(smc + 128 * FST * 2 + 4 * KVB);

    uint32_t sb  = (uint32_t)__cvta_generic_to_shared(smc);
    uint32_t P_u = sb;
    uint32_t K_u = sb + 128 * FST * 2;
    uint32_t V_u = K_u + 2 * KVB;

    int tid = threadIdx.x;
    int warp = tid >> 5, lane = tid & 31;
    int gid = lane >> 2, tig = lane & 3;
    int bh = blockIdx.y, b = bh >> 3, h = bh & 7;
    int m0 = blockIdx.x * 128;
    int wrow = warp * 16;                               // warp owns rows wrow..wrow+15

    const __half* Q  = q + (size_t)b * N_ * C_ + h * HD_;
    const __half* Kp = k + (size_t)b * N_ * C_ + h * HD_;
    const __half* Vp = v + (size_t)b * N_ * C_ + h * HD_;
    const uint8_t* relb = rel8 + (size_t)b * N_ * N_;

    if (tid < 9) tbl[tid] = (tid == 0) ? 0.0f : table[(tid - 1) * H_ + h];

    auto load_kv = [&](int stage, int kn0) {
        uint32_t kb = K_u + stage * KVB;
        uint32_t vb = V_u + stage * KVB;
#pragma unroll
        for (int i = 0; i < 2; i++) {
            int f = tid + i * 256;
            int r = f >> 3, c = (f & 7) << 3;
            cp16(kb + (r * FST + c) * 2, Kp + (size_t)(kn0 + r) * C_ + c);
            cp16(vb + (r * FST + c) * 2, Vp + (size_t)(kn0 + r) * C_ + c);
        }
    };

    // stage Q (128x64) into P region
#pragma unroll
    for (int i = 0; i < 4; i++) {
        int f = tid + i * 256;
        int r = f >> 3, c = (f & 7) << 3;
        cp16(P_u + (r * FST + c) * 2, Q + (size_t)(m0 + r) * C_ + c);
    }
    cp_commit();
    load_kv(0, 0);
    cp_commit();
    cp_wait<1>();
    __syncthreads();

    int li = lane >> 3;
    uint32_t a_off = ((((li & 1) * 8) + (lane & 7)) * FST + (li >> 1) * 8) * 2;
    uint32_t b_off = ((((li >> 1) * 8) + (lane & 7)) * FST + (li & 1) * 8) * 2;

    uint32_t qf[4][4];                                  // 4 k16-steps
    {
        uint32_t qbase = P_u + wrow * FST * 2 + a_off;
#pragma unroll
        for (int ks = 0; ks < 4; ks++)
            ldsm4(qf[ks], qbase + ks * 32);
    }
    __syncthreads();                                    // P region free

    float acc_o[8][4] = {};
    float mprev[2] = {-INFINITY, -INFINITY};
    float lsum[2] = {0.0f, 0.0f};

    for (int kt = 0; kt < N_ / 64; kt++) {
        int cur = kt & 1;
        int kn0 = kt * 64;
        if (kt + 1 < N_ / 64) {
            load_kv(cur ^ 1, (kt + 1) * 64);
            cp_commit();
            cp_wait<1>();
        } else {
            cp_wait<0>();
        }
        __syncthreads();

        // S = Q K^T : 64 kv cols, all in this warp
        float acc_s[8][4] = {};
        {
            uint32_t kb = K_u + cur * KVB + b_off;
#pragma unroll
            for (int ks = 0; ks < 4; ks++) {
                uint32_t bf[4][4];
#pragma unroll
                for (int nb = 0; nb < 4; nb++)
                    ldsm4(bf[nb], kb + nb * (16 * FST * 2) + ks * 32);
#pragma unroll
                for (int ni = 0; ni < 8; ni++)
                    mma_f16(acc_s[ni], qf[ks], &bf[ni >> 1][(ni & 1) * 2]);
            }
        }

        // scale + rel bias + row max (all in regs, row fully in-warp)
        float rmax[2] = {-INFINITY, -INFINITY};
#pragma unroll
        for (int ni = 0; ni < 8; ni++)
#pragma unroll
            for (int e2 = 0; e2 < 2; e2++) {
                int rr = wrow + gid + e2 * 8;
                int col = kn0 + ni * 8 + tig * 2;
                uchar2 rv = *(const uchar2*)&relb[(size_t)(m0 + rr) * N_ + col];
                float v0 = acc_s[ni][e2 * 2]     * 0.125f + tbl[rv.x];
                float v1 = acc_s[ni][e2 * 2 + 1] * 0.125f + tbl[rv.y];
                acc_s[ni][e2 * 2] = v0;
                acc_s[ni][e2 * 2 + 1] = v1;
                rmax[e2] = fmaxf(rmax[e2], fmaxf(v0, v1));
            }
#pragma unroll
        for (int e2 = 0; e2 < 2; e2++) {
            rmax[e2] = fmaxf(rmax[e2], __shfl_xor_sync(0xffffffffu, rmax[e2], 1));
            rmax[e2] = fmaxf(rmax[e2], __shfl_xor_sync(0xffffffffu, rmax[e2], 2));
        }

        // exp + row sum + P->smem fp16; update stats in regs
        float nm[2], fr[2], rsum[2] = {0.0f, 0.0f};
#pragma unroll
        for (int e2 = 0; e2 < 2; e2++) {
            nm[e2] = fmaxf(mprev[e2], rmax[e2]);
            fr[e2] = __expf(mprev[e2] - nm[e2]);
        }
#pragma unroll
        for (int ni = 0; ni < 8; ni++)
#pragma unroll
            for (int e2 = 0; e2 < 2; e2++) {
                float p0 = __expf(acc_s[ni][e2 * 2]     - nm[e2]);
                float p1 = __expf(acc_s[ni][e2 * 2 + 1] - nm[e2]);
                rsum[e2] += p0 + p1;
                int rr = wrow + gid + e2 * 8;
                *(__half2*)&P[rr * FST + ni * 8 + tig * 2] = __floats2half2_rn(p0, p1);
            }
#pragma unroll
        for (int e2 = 0; e2 < 2; e2++) {
            rsum[e2] += __shfl_xor_sync(0xffffffffu, rsum[e2], 1);
            rsum[e2] += __shfl_xor_sync(0xffffffffu, rsum[e2], 2);
            lsum[e2] = lsum[e2] * fr[e2] + rsum[e2];
            mprev[e2] = nm[e2];
        }
        __syncwarp();                                   // P rows visible within warp

        // rescale acc_o
#pragma unroll
        for (int ni = 0; ni < 8; ni++) {
            acc_o[ni][0] *= fr[0]; acc_o[ni][1] *= fr[0];
            acc_o[ni][2] *= fr[1]; acc_o[ni][3] *= fr[1];
        }

        // O += P V  (P rows own-warp; V via ldmatrix.trans on natural [kv][d] tile)
        {
            uint32_t pb = P_u + wrow * FST * 2 + a_off;
            uint32_t vb = V_u + cur * KVB + a_off;
#pragma unroll
            for (int ks = 0; ks < 4; ks++) {
                uint32_t af[4];
                ldsm4(af, pb + ks * 32);
                uint32_t bf[4][4];
#pragma unroll
                for (int nb = 0; nb < 4; nb++)
                    ldsm4t(bf[nb], vb + ks * (16 * FST * 2) + nb * 32);
#pragma unroll
                for (int ni = 0; ni < 8; ni++)
                    mma_f16(acc_o[ni], af, &bf[ni >> 1][(ni & 1) * 2]);
            }
        }
        __syncthreads();                                // release cur stage
    }

    // finalize
#pragma unroll
    for (int ni = 0; ni < 8; ni++)
#pragma unroll
        for (int e2 = 0; e2 < 2; e2++) {
            int rr = wrow + gid + e2 * 8;
            int col = ni * 8 + tig * 2;
            float inv = 1.0f / lsum[e2];
            *(__half2*)&att[((size_t)b * N_ + m0 + rr) * C_ + h * HD_ + col] =
                __floats2half2_rn(acc_o[ni][e2 * 2] * inv, acc_o[ni][e2 * 2 + 1] * inv);
        }
}

// ---------------- launch -----------------------------------------------------------
extern "C" void kernel_launch(void* const* d_in, const int* in_sizes, int n_in,
                              void* d_out, int out_size) {
    const float* x     = (const float*)d_in[0];
    const int*   eidx  = (const int*)  d_in[1];
    const int*   etype = (const int*)  d_in[2];
    const float* q_w   = (const float*)d_in[3];
    const float* q_b   = (const float*)d_in[4];
    const float* k_w   = (const float*)d_in[5];
    const float* k_b   = (const float*)d_in[6];
    const float* v_w   = (const float*)d_in[7];
    const float* v_b   = (const float*)d_in[8];
    const float* o_w   = (const float*)d_in[9];
    const float* o_b   = (const float*)d_in[10];
    const float* table = (const float*)d_in[11];
    const float* ln1_g = (const float*)d_in[12];
    const float* ln1_b = (const float*)d_in[13];
    const float* ln2_g = (const float*)d_in[14];
    const float* ln2_b = (const float*)d_in[15];
    const float* f1_w  = (const float*)d_in[16];
    const float* f1_b  = (const float*)d_in[17];
    const float* f2_w  = (const float*)d_in[18];
    const float* f2_b  = (const float*)d_in[19];
    float* out = (float*)d_out;

    void *p_rel8, *p_h, *p_q, *p_k, *p_v, *p_att, *p_res, *p_h2, *p_mid;
    void *p_wq, *p_wk, *p_wv, *p_wo, *p_f1, *p_f2;
    cudaGetSymbolAddress(&p_rel8, g_rel8);
    cudaGetSymbolAddress(&p_h,   g_h);
    cudaGetSymbolAddress(&p_q,   g_q);
    cudaGetSymbolAddress(&p_k,   g_k);
    cudaGetSymbolAddress(&p_v,   g_v);
    cudaGetSymbolAddress(&p_att, g_att);
    cudaGetSymbolAddress(&p_res, g_res);
    cudaGetSymbolAddress(&p_h2,  g_h2);
    cudaGetSymbolAddress(&p_mid, g_mid);
    cudaGetSymbolAddress(&p_wq,  g_wqT);
    cudaGetSymbolAddress(&p_wk,  g_wkT);
    cudaGetSymbolAddress(&p_wv,  g_wvT);
    cudaGetSymbolAddress(&p_wo,  g_woT);
    cudaGetSymbolAddress(&p_f1,  g_f1T);
    cudaGetSymbolAddress(&p_f2,  g_f2T);

    const int SMEM_MM    = 2 * (256 * WST * 2);                   // 73728
    const int SMEM_FLASH = 128 * FST * 2 + 4 * KVB + 16 * 4;      // ~55.4 KB
    cudaFuncSetAttribute(mm_tc<EPI_BIAS>, cudaFuncAttributeMaxDynamicSharedMemorySize, SMEM_MM);
    cudaFuncSetAttribute(mm_tc<EPI_RES>,  cudaFuncAttributeMaxDynamicSharedMemorySize, SMEM_MM);
    cudaFuncSetAttribute(mm_tc<EPI_GELU>, cudaFuncAttributeMaxDynamicSharedMemorySize, SMEM_MM);
    cudaFuncSetAttribute(flash_attn_kernel, cudaFuncAttributeMaxDynamicSharedMemorySize, SMEM_FLASH);

    const int rows = B_ * N_;
    __half* fh  = (__half*)p_h;  __half* fq = (__half*)p_q;  __half* fk = (__half*)p_k;
    __half* fv  = (__half*)p_v;
    __half* fatt = (__half*)p_att; float* fres = (float*)p_res;
    __half* fh2 = (__half*)p_h2; __half* fmid = (__half*)p_mid;

    // 1) weight prep
    transpose_all_kernel<<<3072, 256>>>(q_w, k_w, v_w, o_w, f1_w, f2_w);
    // 2) LN1
    ln_kernel<<<rows, 256>>>(x, ln1_g, ln1_b, fh);
    // 3) zero rel8
    init_rel8_kernel<<<1024, 256>>>((uint4*)p_rel8);
    // 4) fused QKV  (profile slot)
    mm_tc<EPI_BIAS><<<dim3(C_ / 128, rows / 128, 3), 256, SMEM_MM>>>(
        fh, (__half*)p_wq, (__half*)p_wk, (__half*)p_wv, q_b, k_b, v_b, nullptr,
        fq, fk, fv, C_, C_, C_, C_);
    // 5) scatter edges
    scatter_edges8_kernel<<<(B_ * E_) / 256, 256>>>(eidx, etype, (unsigned int*)p_rel8);
    // 6) fused attention
    flash_attn_kernel<<<dim3(N_ / 128, B_ * H_), 256, SMEM_FLASH>>>(
        fq, fk, fv, (const uint8_t*)p_rel8, table, fatt);
    // 7) output projection + residual(x)
    mm_tc<EPI_RES><<<dim3(C_ / 128, rows / 128, 1), 256, SMEM_MM>>>(
        fatt, (__half*)p_wo, nullptr, nullptr, o_b, nullptr, nullptr, x,
        fres, nullptr, nullptr, C_, C_, C_, C_);
    // 8) LN2
    ln_kernel<<<rows, 256>>>(fres, ln2_g, ln2_b, fh2);
    // 9-10) FFN
    mm_tc<EPI_GELU><<<dim3(FF_ / 128, rows / 128, 1), 256, SMEM_MM>>>(
        fh2, (__half*)p_f1, nullptr, nullptr, f1_b, nullptr, nullptr, nullptr,
        fmid, nullptr, nullptr, C_, C_, C_, FF_);
    mm_tc<EPI_RES><<<dim3(C_ / 128, rows / 128, 1), 256, SMEM_MM>>>(
        fmid, (__half*)p_f2, nullptr, nullptr, f2_b, nullptr, nullptr, fres,
        out, nullptr, nullptr, FF_, FF_, FF_, C_);
}